// round 7
// baseline (speedup 1.0000x reference)
#include <cuda_runtime.h>
#include <cuda_bf16.h>
#include <cstdint>
#include <math.h>

#define BB 8
#define CC 512
#define LLEN 2048
#define NGRP 8
#define CPG 64
#define CL (CC*LLEN)

// ---------------- scratch ----------------
__device__ __nv_bfloat16 g_hTh[(size_t)BB*CL], g_hTl[(size_t)BB*CL];     // hT [B][L][C]
__device__ __nv_bfloat16 g_qkh[(size_t)BB*LLEN*1024], g_qkl[(size_t)BB*LLEN*1024]; // [B][L][1024] q|k
__device__ __nv_bfloat16 g_vh [(size_t)BB*CL], g_vl [(size_t)BB*CL];     // v  [B][C][L]
__device__ __nv_bfloat16 g_h2h[(size_t)BB*CL], g_h2l[(size_t)BB*CL];     // h2T[B][L][C]
__device__ __nv_bfloat16 g_sh [(size_t)BB*LLEN*LLEN], g_sl[(size_t)BB*LLEN*LLEN];
__device__ __nv_bfloat16 g_wh [4*CC*CC], g_wl[4*CC*CC];                  // wq,wk,wv,wo
__device__ float g_bqk[1024];
__device__ float g_stats[BB*NGRP*2];

// ---------------- helpers ----------------
__device__ __forceinline__ uint32_t smem_u32(const void* p){
    uint32_t a;
    asm("{ .reg .u64 t; cvta.to.shared.u64 t, %1; cvt.u32.u64 %0, t; }" : "=r"(a) : "l"(p));
    return a;
}
__device__ __forceinline__ void cp16(uint32_t s, const void* g){
    asm volatile("cp.async.cg.shared.global [%0], [%1], 16;" :: "r"(s), "l"(g));
}
#define CP_COMMIT() asm volatile("cp.async.commit_group;" ::: "memory")
#define CP_WAIT2()  asm volatile("cp.async.wait_group 2;" ::: "memory")
#define CP_WAIT1()  asm volatile("cp.async.wait_group 1;" ::: "memory")
#define CP_WAIT0()  asm volatile("cp.async.wait_group 0;" ::: "memory")

#define LDX4(r0,r1,r2,r3,addr) \
    asm volatile("ldmatrix.sync.aligned.m8n8.x4.shared.b16 {%0,%1,%2,%3}, [%4];" \
        : "=r"(r0), "=r"(r1), "=r"(r2), "=r"(r3) : "r"(addr))

#define MMA16816(d, a, b) \
    asm volatile("mma.sync.aligned.m16n8k16.row.col.f32.bf16.bf16.f32 " \
        "{%0,%1,%2,%3}, {%4,%5,%6,%7}, {%8,%9}, {%0,%1,%2,%3};" \
        : "+f"((d)[0]), "+f"((d)[1]), "+f"((d)[2]), "+f"((d)[3]) \
        : "r"((a)[0]), "r"((a)[1]), "r"((a)[2]), "r"((a)[3]), "r"((b)[0]), "r"((b)[1]))

__device__ __forceinline__ void split2pack(float v0, float v1, uint32_t& hi, uint32_t& lo){
    uint32_t u0 = __float_as_uint(v0) & 0xffff0000u;
    uint32_t u1 = __float_as_uint(v1) & 0xffff0000u;
    hi = (u0 >> 16) | u1;
    float r0 = v0 - __uint_as_float(u0);
    float r1 = v1 - __uint_as_float(u1);
    asm("cvt.rn.bf16x2.f32 %0, %1, %2;" : "=r"(lo) : "f"(r1), "f"(r0));
}
__device__ __forceinline__ void split1(float v, __nv_bfloat16* hp, __nv_bfloat16* lp){
    uint32_t u = __float_as_uint(v) & 0xffff0000u;
    *(unsigned short*)hp = (unsigned short)(u >> 16);
    *lp = __float2bfloat16(v - __uint_as_float(u));
}

// ---------------- HMMA GEMM: tile 256x128, 256 threads, warp 64x64, BK=32, 4-stage ----------------
#define OFF_AH 0
#define OFF_AL 16384
#define OFF_BH 32768
#define OFF_BL 40960
#define STG_B  49152
#define NSTAGE 4
#define DYN_SMEM (NSTAGE*STG_B + 128)

__global__ void __launch_bounds__(256, 1)
hmma_gemm(const __nv_bfloat16* __restrict__ Ah, const __nv_bfloat16* __restrict__ Al,
          const __nv_bfloat16* __restrict__ Bh, const __nv_bfloat16* __restrict__ Bl,
          int K, int lda, int ldb, int ldc, long sA, long sB, long sC,
          float* __restrict__ Cf, __nv_bfloat16* __restrict__ Ch, __nv_bfloat16* __restrict__ Cl,
          const float* __restrict__ biasM, const float* __restrict__ biasN,
          const float* __restrict__ resid, float scale)
{
    extern __shared__ char dsm[];
    const uint32_t sbase = (smem_u32(dsm) + 127u) & ~127u;
    const int tid = threadIdx.x, lane = tid & 31, wid = tid >> 5;
    const int warpM = (wid & 3) * 64, warpN = (wid >> 2) * 64;
    const int bz = blockIdx.z;
    Ah += (size_t)bz * sA;  Al += (size_t)bz * sA;
    Bh += (size_t)bz * sB;  Bl += (size_t)bz * sB;
    if (Cf)    Cf    += (size_t)bz * sC;
    if (Ch)  { Ch    += (size_t)bz * sC; Cl += (size_t)bz * sC; }
    if (resid) resid += (size_t)bz * sC;
    const int m0 = blockIdx.y * 256, n0 = blockIdx.x * 128;
    const int niter = K >> 5;

    // cp.async: 12 chunks/thread. row = tid>>2, seg = tid&3 (16B each), 64B rows
    const int c_row = tid >> 2, c_seg = tid & 3;
    const uint32_t c_cb = (uint32_t)(c_seg * 16);

    auto issue = [&](int kt){
        const int kk = kt * 32;
        const uint32_t sb = sbase + (kt & (NSTAGE-1)) * STG_B;
        #pragma unroll
        for (int j = 0; j < 4; j++){               // A rows: 4 groups of 64
            const int row = c_row + j * 64;
            const uint32_t sw = (uint32_t)(((row >> 1) & 3) << 4);
            const uint32_t d = sb + row * 64 + (c_cb ^ sw);
            const size_t ga = (size_t)(m0 + row) * lda + kk + c_seg * 8;
            cp16(d + OFF_AH, Ah + ga);
            cp16(d + OFF_AL, Al + ga);
        }
        #pragma unroll
        for (int j = 0; j < 2; j++){               // B rows: 2 groups of 64
            const int row = c_row + j * 64;
            const uint32_t sw = (uint32_t)(((row >> 1) & 3) << 4);
            const uint32_t d = sb + row * 64 + (c_cb ^ sw);
            const size_t gb = (size_t)(n0 + row) * ldb + kk + c_seg * 8;
            cp16(d + OFF_BH, Bh + gb);
            cp16(d + OFF_BL, Bl + gb);
        }
        CP_COMMIT();
    };

    float acc[4][8][4];
    #pragma unroll
    for (int i = 0; i < 4; i++)
        #pragma unroll
        for (int j = 0; j < 8; j++)
            #pragma unroll
            for (int t = 0; t < 4; t++) acc[i][j][t] = 0.f;

    // ldmatrix lane addressing (64B rows); +16 rows preserves swizzle
    const int aRow0 = warpM + (lane & 15);
    const uint32_t aSw = (uint32_t)(((aRow0 >> 1) & 3) << 4);
    const uint32_t aC  = (uint32_t)((lane >> 4) << 4);
    const int bRow0 = warpN + ((lane >> 4) << 3) + (lane & 7);
    const uint32_t bSw = (uint32_t)(((bRow0 >> 1) & 3) << 4);
    const uint32_t bC  = (uint32_t)(((lane >> 3) & 1) << 4);

    issue(0); issue(1); issue(2);

    for (int kt = 0; kt < niter; kt++){
        if (kt + 2 < niter)      CP_WAIT2();
        else if (kt + 1 < niter) CP_WAIT1();
        else                     CP_WAIT0();
        __syncthreads();
        if (kt + 3 < niter) issue(kt + 3);
        const uint32_t sb = sbase + (kt & (NSTAGE-1)) * STG_B;

        #pragma unroll
        for (int ko = 0; ko < 2; ko++){
            const uint32_t kb = (uint32_t)(ko * 32);
            uint32_t a_h[4][4], a_l[4][4], b_h[4][4], b_l[4][4];
            #pragma unroll
            for (int p = 0; p < 4; p++){
                uint32_t bd = sb + (uint32_t)((bRow0 + p*16) * 64) + ((kb + bC) ^ bSw);
                LDX4(b_h[p][0], b_h[p][1], b_h[p][2], b_h[p][3], bd + OFF_BH);
                LDX4(b_l[p][0], b_l[p][1], b_l[p][2], b_l[p][3], bd + OFF_BL);
            }
            #pragma unroll
            for (int mt = 0; mt < 4; mt++){
                uint32_t ad = sb + (uint32_t)((aRow0 + mt*16) * 64) + ((kb + aC) ^ aSw);
                LDX4(a_h[mt][0], a_h[mt][1], a_h[mt][2], a_h[mt][3], ad + OFF_AH);
                LDX4(a_l[mt][0], a_l[mt][1], a_l[mt][2], a_l[mt][3], ad + OFF_AL);
            }
            #pragma unroll
            for (int mt = 0; mt < 4; mt++)
                #pragma unroll
                for (int nt = 0; nt < 8; nt++){
                    uint32_t* bh = &b_h[nt >> 1][(nt & 1) * 2];
                    uint32_t* bl = &b_l[nt >> 1][(nt & 1) * 2];
                    MMA16816(acc[mt][nt], a_h[mt], bh);
                    MMA16816(acc[mt][nt], a_h[mt], bl);
                    MMA16816(acc[mt][nt], a_l[mt], bh);
                }
        }
    }

    // ---- epilogue ----
    #pragma unroll
    for (int mt = 0; mt < 4; mt++){
        const int r0 = m0 + warpM + mt * 16 + (lane >> 2);
        const int r1 = r0 + 8;
        const float bm0 = biasM ? biasM[r0] : 0.f;
        const float bm1 = biasM ? biasM[r1] : 0.f;
        #pragma unroll
        for (int nt = 0; nt < 8; nt++){
            const int c = n0 + warpN + nt * 8 + ((lane & 3) << 1);
            float v0 = acc[mt][nt][0] * scale + bm0;
            float v1 = acc[mt][nt][1] * scale + bm0;
            float v2 = acc[mt][nt][2] * scale + bm1;
            float v3 = acc[mt][nt][3] * scale + bm1;
            if (biasN){
                float2 bn = *(const float2*)&biasN[c];
                v0 += bn.x; v1 += bn.y; v2 += bn.x; v3 += bn.y;
            }
            const size_t o0 = (size_t)r0 * ldc + c;
            const size_t o1 = (size_t)r1 * ldc + c;
            if (resid){
                float2 x0 = *(const float2*)&resid[o0];
                float2 x1 = *(const float2*)&resid[o1];
                v0 += x0.x; v1 += x0.y; v2 += x1.x; v3 += x1.y;
            }
            if (Cf){
                *(float2*)&Cf[o0] = make_float2(v0, v1);
                *(float2*)&Cf[o1] = make_float2(v2, v3);
            }
            if (Ch){
                uint32_t h01, l01, h23, l23;
                split2pack(v0, v1, h01, l01);
                split2pack(v2, v3, h23, l23);
                *(uint32_t*)&Ch[o0] = h01;  *(uint32_t*)&Cl[o0] = l01;
                *(uint32_t*)&Ch[o1] = h23;  *(uint32_t*)&Cl[o1] = l23;
            }
        }
    }
}

// ---------------- weight convert ----------------
__global__ void __launch_bounds__(256) wconv(const float* __restrict__ w0, const float* __restrict__ w1,
                                             const float* __restrict__ w2, const float* __restrict__ w3,
                                             __nv_bfloat16* __restrict__ hi, __nv_bfloat16* __restrict__ lo)
{
    int i = blockIdx.x * 256 + threadIdx.x;
    int w = i >> 16;
    int off = (i & 65535) * 4;
    const float* src = (w == 0) ? w0 : (w == 1) ? w1 : (w == 2) ? w2 : w3;
    float4 v = *(const float4*)(src + off);
    uint32_t h01, l01, h23, l23;
    split2pack(v.x, v.y, h01, l01);
    split2pack(v.z, v.w, h23, l23);
    size_t o = (size_t)w * CC * CC + off;
    *(uint32_t*)&hi[o]   = h01;  *(uint32_t*)&lo[o]   = l01;
    *(uint32_t*)&hi[o+2] = h23;  *(uint32_t*)&lo[o+2] = l23;
}

__global__ void bcat(const float* __restrict__ bq, const float* __restrict__ bk,
                     float* __restrict__ o)
{
    int i = blockIdx.x * 256 + threadIdx.x;
    if (i < 512) o[i] = bq[i];
    else if (i < 1024) o[i] = bk[i - 512];
}

// ---------------- GroupNorm stats ----------------
__global__ void __launch_bounds__(1024) gn_stats(const float* __restrict__ x, float* __restrict__ stats)
{
    int b = blockIdx.x >> 3, g = blockIdx.x & 7;
    const float* xp = x + ((size_t)b*CC + (size_t)g*CPG) * LLEN;
    const int n = CPG * LLEN;
    int tid = threadIdx.x;
    float s = 0.f, ss = 0.f;
    for (int i = tid; i < n; i += 1024){ float v = xp[i]; s += v; ss += v*v; }
    __shared__ float rs[32], rss[32];
    #pragma unroll
    for (int o = 16; o; o >>= 1){
        s  += __shfl_xor_sync(0xffffffffu, s,  o);
        ss += __shfl_xor_sync(0xffffffffu, ss, o);
    }
    if ((tid & 31) == 0){ rs[tid>>5] = s; rss[tid>>5] = ss; }
    __syncthreads();
    if (tid == 0){
        float t = 0.f, t2 = 0.f;
        #pragma unroll
        for (int i = 0; i < 32; i++){ t += rs[i]; t2 += rss[i]; }
        float mean = t / (float)n;
        float var  = t2 / (float)n - mean*mean;
        stats[blockIdx.x*2]   = mean;
        stats[blockIdx.x*2+1] = rsqrtf(var + 1e-6f);
    }
}

// ---------------- GroupNorm apply + transpose -> hT hi/lo ----------------
__global__ void __launch_bounds__(256) gn_apply_t(const float* __restrict__ x,
                                                  const float* __restrict__ stats,
                                                  const float* __restrict__ gamma,
                                                  const float* __restrict__ beta,
                                                  __nv_bfloat16* __restrict__ hTh,
                                                  __nv_bfloat16* __restrict__ hTl)
{
    __shared__ float tile[64][33];
    int b = blockIdx.z, g = blockIdx.y, l0 = blockIdx.x * 32;
    float mean = stats[(b*NGRP+g)*2], inv = stats[(b*NGRP+g)*2+1];
    const float* xp = x + ((size_t)b*CC + (size_t)g*CPG) * LLEN;
    int tid = threadIdx.x;
    #pragma unroll
    for (int i = 0; i < 8; i++){
        int idx = tid + i*256; int c = idx >> 5, l = idx & 31;
        float v = xp[(size_t)c*LLEN + l0 + l];
        tile[c][l] = (v - mean) * inv * gamma[g*CPG + c] + beta[g*CPG + c];
    }
    __syncthreads();
    size_t base = (size_t)b * LLEN * CC;
    #pragma unroll
    for (int i = 0; i < 8; i++){
        int idx = tid + i*256; int l = idx >> 6, c = idx & 63;
        size_t o = base + (size_t)(l0 + l)*CC + g*CPG + c;
        split1(tile[c][l], &hTh[o], &hTl[o]);
    }
}

// ---------------- row softmax over bf16 hi/lo pair, vectorized ----------------
__global__ void __launch_bounds__(256) softmax_kernel(__nv_bfloat16* __restrict__ Sh,
                                                      __nv_bfloat16* __restrict__ Sl)
{
    size_t ob = (size_t)blockIdx.x * LLEN;
    int tid = threadIdx.x;
    int base = tid * 8;
    uint4 hv = *(uint4*)&Sh[ob + base];
    uint4 lv = *(uint4*)&Sl[ob + base];
    float v[8];
    {
        uint32_t hw[4] = {hv.x, hv.y, hv.z, hv.w};
        uint32_t lw[4] = {lv.x, lv.y, lv.z, lv.w};
        #pragma unroll
        for (int i = 0; i < 4; i++){
            v[2*i]   = __uint_as_float(hw[i] << 16)          + __uint_as_float(lw[i] << 16);
            v[2*i+1] = __uint_as_float(hw[i] & 0xffff0000u)  + __uint_as_float(lw[i] & 0xffff0000u);
        }
    }
    float mx = -1e30f;
    #pragma unroll
    for (int i = 0; i < 8; i++) mx = fmaxf(mx, v[i]);
    __shared__ float rmax[8], rsum[8];
    #pragma unroll
    for (int o = 16; o; o >>= 1) mx = fmaxf(mx, __shfl_xor_sync(0xffffffffu, mx, o));
    if ((tid & 31) == 0) rmax[tid >> 5] = mx;
    __syncthreads();
    float m = rmax[0];
    #pragma unroll
    for (int i = 1; i < 8; i++) m = fmaxf(m, rmax[i]);
    float sm = 0.f;
    #pragma unroll
    for (int i = 0; i < 8; i++){ v[i] = __expf(v[i] - m); sm += v[i]; }
    #pragma unroll
    for (int o = 16; o; o >>= 1) sm += __shfl_xor_sync(0xffffffffu, sm, o);
    if ((tid & 31) == 0) rsum[tid >> 5] = sm;
    __syncthreads();
    float tot = 0.f;
    #pragma unroll
    for (int i = 0; i < 8; i++) tot += rsum[i];
    float inv = 1.f / tot;
    uint32_t ho[4], lo[4];
    #pragma unroll
    for (int i = 0; i < 4; i++)
        split2pack(v[2*i] * inv, v[2*i+1] * inv, ho[i], lo[i]);
    *(uint4*)&Sh[ob + base] = make_uint4(ho[0], ho[1], ho[2], ho[3]);
    *(uint4*)&Sl[ob + base] = make_uint4(lo[0], lo[1], lo[2], lo[3]);
}

// ---------------- launch ----------------
extern "C" void kernel_launch(void* const* d_in, const int* in_sizes, int n_in,
                              void* d_out, int out_size)
{
    const float* x     = (const float*)d_in[0];
    const float* gamma = (const float*)d_in[1];
    const float* beta  = (const float*)d_in[2];
    const float* wq    = (const float*)d_in[3];
    const float* bq    = (const float*)d_in[4];
    const float* wk    = (const float*)d_in[5];
    const float* bk    = (const float*)d_in[6];
    const float* wv    = (const float*)d_in[7];
    const float* bv    = (const float*)d_in[8];
    const float* wo    = (const float*)d_in[9];
    const float* bo    = (const float*)d_in[10];
    float* out = (float*)d_out;

    __nv_bfloat16 *hTh,*hTl,*qkh,*qkl,*vh,*vl,*h2h,*h2l,*sh,*sl,*wh,*wl;
    float *stats, *bqk;
    cudaGetSymbolAddress((void**)&hTh, g_hTh); cudaGetSymbolAddress((void**)&hTl, g_hTl);
    cudaGetSymbolAddress((void**)&qkh, g_qkh); cudaGetSymbolAddress((void**)&qkl, g_qkl);
    cudaGetSymbolAddress((void**)&vh,  g_vh);  cudaGetSymbolAddress((void**)&vl,  g_vl);
    cudaGetSymbolAddress((void**)&h2h, g_h2h); cudaGetSymbolAddress((void**)&h2l, g_h2l);
    cudaGetSymbolAddress((void**)&sh,  g_sh);  cudaGetSymbolAddress((void**)&sl,  g_sl);
    cudaGetSymbolAddress((void**)&wh,  g_wh);  cudaGetSymbolAddress((void**)&wl,  g_wl);
    cudaGetSymbolAddress((void**)&stats, g_stats);
    cudaGetSymbolAddress((void**)&bqk, g_bqk);

    cudaFuncSetAttribute(hmma_gemm, cudaFuncAttributeMaxDynamicSharedMemorySize, DYN_SMEM);

    const long LL  = (long)LLEN * LLEN;
    const long LQK = (long)LLEN * 1024;
    const float scl = 1.0f / sqrtf((float)CC);

    gn_stats<<<BB*NGRP, 1024>>>(x, stats);
    wconv<<<1024, 256>>>(wq, wk, wv, wo, wh, wl);
    bcat<<<4, 256>>>(bq, bk, bqk);
    gn_apply_t<<<dim3(LLEN/32, NGRP, BB), 256>>>(x, stats, gamma, beta, hTh, hTl);

    dim3 blk(256);
    // qk[l,n] = sum hT[l,:]*w_qk[n,:] + bqk[n]   M=2048, N=1024, K=512
    hmma_gemm<<<dim3(8,8,BB), blk, DYN_SMEM>>>(hTh, hTl, wh, wl,
        CC, CC, CC, 1024, (long)CL, 0L, LQK, nullptr, qkh, qkl, nullptr, bqk, nullptr, 1.f);
    // v[c,l] = sum wv[c,:]*hT[l,:] + bv[c]       M=512, N=2048, K=512
    hmma_gemm<<<dim3(16,2,BB), blk, DYN_SMEM>>>(wh + 2*CC*CC, wl + 2*CC*CC, hTh, hTl,
        CC, CC, CC, LLEN, 0L, (long)CL, (long)CL, nullptr, vh, vl, bv, nullptr, nullptr, 1.f);
    // S[i,j] = scl * sum q[i,:]*k[j,:]           M=N=2048, K=512
    hmma_gemm<<<dim3(16,8,BB), blk, DYN_SMEM>>>(qkh, qkl, qkh + 512, qkl + 512,
        CC, 1024, 1024, LLEN, LQK, LQK, LL, nullptr, sh, sl, nullptr, nullptr, nullptr, scl);

    softmax_kernel<<<BB*LLEN, 256>>>(sh, sl);

    // h2T[i,c] = sum S[i,:]*v[c,:]               M=2048, N=512, K=2048
    hmma_gemm<<<dim3(4,8,BB), blk, DYN_SMEM>>>(sh, sl, vh, vl,
        LLEN, LLEN, LLEN, CC, LL, (long)CL, (long)CL, nullptr, h2h, h2l, nullptr, nullptr, nullptr, 1.f);
    // out[c,l] = x + sum wo[c,:]*h2T[l,:] + bo   M=512, N=2048, K=512
    hmma_gemm<<<dim3(16,2,BB), blk, DYN_SMEM>>>(wh + 3*CC*CC, wl + 3*CC*CC, h2h, h2l,
        CC, CC, CC, LLEN, 0L, (long)CL, (long)CL, out, nullptr, nullptr, bo, nullptr, x, 1.f);
}

// round 8
// speedup vs baseline: 1.1644x; 1.1644x over previous
#include <cuda_runtime.h>
#include <cuda_bf16.h>
#include <cuda_fp16.h>
#include <cstdint>
#include <math.h>

#define BB 8
#define CC 512
#define LLEN 2048
#define NGRP 8
#define CPG 64
#define CL (CC*LLEN)
typedef unsigned short u16;

// ---------------- scratch (raw 16-bit halves; fp16 or bf16 per stage) ----------------
__device__ u16 g_hTh[(size_t)BB*CL], g_hTl[(size_t)BB*CL];     // hT [B][L][C]  bf16 pair
__device__ u16 g_qkh[(size_t)BB*LLEN*1024], g_qkl[(size_t)BB*LLEN*1024]; // q|k fp16 pair
__device__ u16 g_vh [(size_t)BB*CL], g_vl [(size_t)BB*CL];     // v  [B][C][L]  fp16 pair
__device__ u16 g_h2h[(size_t)BB*CL], g_h2l[(size_t)BB*CL];     // h2T bf16 pair
__device__ u16 g_sh [(size_t)BB*LLEN*LLEN], g_sl[(size_t)BB*LLEN*LLEN]; // S fp16 pair
__device__ u16 g_wh [4*CC*CC], g_wl[4*CC*CC];                  // weights bf16 pair
__device__ float g_bqk[1024];
__device__ float g_stats[BB*NGRP*2];

// ---------------- helpers ----------------
__device__ __forceinline__ uint32_t smem_u32(const void* p){
    uint32_t a;
    asm("{ .reg .u64 t; cvta.to.shared.u64 t, %1; cvt.u32.u64 %0, t; }" : "=r"(a) : "l"(p));
    return a;
}
__device__ __forceinline__ void cp16(uint32_t s, const void* g){
    asm volatile("cp.async.cg.shared.global [%0], [%1], 16;" :: "r"(s), "l"(g));
}
#define CP_COMMIT() asm volatile("cp.async.commit_group;" ::: "memory")
#define CP_WAIT2()  asm volatile("cp.async.wait_group 2;" ::: "memory")
#define CP_WAIT1()  asm volatile("cp.async.wait_group 1;" ::: "memory")
#define CP_WAIT0()  asm volatile("cp.async.wait_group 0;" ::: "memory")

#define LDX4(r0,r1,r2,r3,addr) \
    asm volatile("ldmatrix.sync.aligned.m8n8.x4.shared.b16 {%0,%1,%2,%3}, [%4];" \
        : "=r"(r0), "=r"(r1), "=r"(r2), "=r"(r3) : "r"(addr))

#define MMA_BF16(d, a, b) \
    asm volatile("mma.sync.aligned.m16n8k16.row.col.f32.bf16.bf16.f32 " \
        "{%0,%1,%2,%3}, {%4,%5,%6,%7}, {%8,%9}, {%0,%1,%2,%3};" \
        : "+f"((d)[0]), "+f"((d)[1]), "+f"((d)[2]), "+f"((d)[3]) \
        : "r"((a)[0]), "r"((a)[1]), "r"((a)[2]), "r"((a)[3]), "r"((b)[0]), "r"((b)[1]))
#define MMA_F16(d, a, b) \
    asm volatile("mma.sync.aligned.m16n8k16.row.col.f32.f16.f16.f32 " \
        "{%0,%1,%2,%3}, {%4,%5,%6,%7}, {%8,%9}, {%0,%1,%2,%3};" \
        : "+f"((d)[0]), "+f"((d)[1]), "+f"((d)[2]), "+f"((d)[3]) \
        : "r"((a)[0]), "r"((a)[1]), "r"((a)[2]), "r"((a)[3]), "r"((b)[0]), "r"((b)[1]))

// bf16 split: hi = truncate (exact residual), lo = rn(x-hi)
__device__ __forceinline__ void split2pack_bf(float v0, float v1, uint32_t& hi, uint32_t& lo){
    uint32_t u0 = __float_as_uint(v0) & 0xffff0000u;
    uint32_t u1 = __float_as_uint(v1) & 0xffff0000u;
    hi = (u0 >> 16) | u1;
    float r0 = v0 - __uint_as_float(u0);
    float r1 = v1 - __uint_as_float(u1);
    asm("cvt.rn.bf16x2.f32 %0, %1, %2;" : "=r"(lo) : "f"(r1), "f"(r0));
}
// fp16 split: hi = rn(x), residual exact in fp32, lo = rn(residual)
__device__ __forceinline__ void split2pack_f16(float v0, float v1, uint32_t& hi, uint32_t& lo){
    __half h0 = __float2half_rn(v0), h1 = __float2half_rn(v1);
    float r0 = v0 - __half2float(h0);
    float r1 = v1 - __half2float(h1);
    __half l0 = __float2half_rn(r0), l1 = __float2half_rn(r1);
    hi = (uint32_t)__half_as_ushort(h0) | ((uint32_t)__half_as_ushort(h1) << 16);
    lo = (uint32_t)__half_as_ushort(l0) | ((uint32_t)__half_as_ushort(l1) << 16);
}
__device__ __forceinline__ void split1_bf(float v, u16* hp, u16* lp){
    uint32_t u = __float_as_uint(v) & 0xffff0000u;
    *hp = (u16)(u >> 16);
    *lp = __bfloat16_as_ushort(__float2bfloat16(v - __uint_as_float(u)));
}

// ---------------- HMMA GEMM: tile 256x128, 256 thr, warp 64x64, BK=32, 4-stage ----------------
// NPROD=3: bf16 inputs, D += AhBh + AhBl + AlBh.  NPROD=2: fp16 inputs, D += AhB + AlB (B=Bh).
// OUTF16: half-pair output format (1=fp16 split, 0=bf16 split).
#define OFF_AH 0
#define OFF_AL 16384
#define OFF_BH 32768
#define OFF_BL 40960
#define NSTAGE 4

template<int NPROD, int OUTF16>
__global__ void __launch_bounds__(256, 1)
hmma_gemm(const u16* __restrict__ Ah, const u16* __restrict__ Al,
          const u16* __restrict__ Bh, const u16* __restrict__ Bl,
          int K, int lda, int ldb, int ldc, long sA, long sB, long sC,
          float* __restrict__ Cf, u16* __restrict__ Ch, u16* __restrict__ Cl,
          const float* __restrict__ biasM, const float* __restrict__ biasN,
          const float* __restrict__ resid, float scale)
{
    constexpr uint32_t STG = (NPROD == 3) ? 49152 : 40960;
    extern __shared__ char dsm[];
    const uint32_t sbase = (smem_u32(dsm) + 127u) & ~127u;
    const int tid = threadIdx.x, lane = tid & 31, wid = tid >> 5;
    const int warpM = (wid & 3) * 64, warpN = (wid >> 2) * 64;
    const int bz = blockIdx.z;
    Ah += (size_t)bz * sA;  Al += (size_t)bz * sA;
    Bh += (size_t)bz * sB;  if (NPROD == 3) Bl += (size_t)bz * sB;
    if (Cf)    Cf    += (size_t)bz * sC;
    if (Ch)  { Ch    += (size_t)bz * sC; Cl += (size_t)bz * sC; }
    if (resid) resid += (size_t)bz * sC;
    const int m0 = blockIdx.y * 256, n0 = blockIdx.x * 128;
    const int niter = K >> 5;

    const int c_row = tid >> 2, c_seg = tid & 3;
    const uint32_t c_cb = (uint32_t)(c_seg * 16);

    auto issue = [&](int kt){
        const int kk = kt * 32;
        const uint32_t sb = sbase + (kt & (NSTAGE-1)) * STG;
        #pragma unroll
        for (int j = 0; j < 4; j++){               // A rows: 4 groups of 64
            const int row = c_row + j * 64;
            const uint32_t sw = (uint32_t)(((row >> 1) & 3) << 4);
            const uint32_t d = sb + row * 64 + (c_cb ^ sw);
            const size_t ga = (size_t)(m0 + row) * lda + kk + c_seg * 8;
            cp16(d + OFF_AH, Ah + ga);
            cp16(d + OFF_AL, Al + ga);
        }
        #pragma unroll
        for (int j = 0; j < 2; j++){               // B rows: 2 groups of 64
            const int row = c_row + j * 64;
            const uint32_t sw = (uint32_t)(((row >> 1) & 3) << 4);
            const uint32_t d = sb + row * 64 + (c_cb ^ sw);
            const size_t gb = (size_t)(n0 + row) * ldb + kk + c_seg * 8;
            cp16(d + OFF_BH, Bh + gb);
            if (NPROD == 3) cp16(d + OFF_BL, Bl + gb);
        }
        CP_COMMIT();
    };

    float acc[4][8][4];
    #pragma unroll
    for (int i = 0; i < 4; i++)
        #pragma unroll
        for (int j = 0; j < 8; j++)
            #pragma unroll
            for (int t = 0; t < 4; t++) acc[i][j][t] = 0.f;

    const int aRow0 = warpM + (lane & 15);
    const uint32_t aSw = (uint32_t)(((aRow0 >> 1) & 3) << 4);
    const uint32_t aC  = (uint32_t)((lane >> 4) << 4);
    const int bRow0 = warpN + ((lane >> 4) << 3) + (lane & 7);
    const uint32_t bSw = (uint32_t)(((bRow0 >> 1) & 3) << 4);
    const uint32_t bC  = (uint32_t)(((lane >> 3) & 1) << 4);

    issue(0); issue(1); issue(2);

    for (int kt = 0; kt < niter; kt++){
        if (kt + 2 < niter)      CP_WAIT2();
        else if (kt + 1 < niter) CP_WAIT1();
        else                     CP_WAIT0();
        __syncthreads();
        if (kt + 3 < niter) issue(kt + 3);
        const uint32_t sb = sbase + (kt & (NSTAGE-1)) * STG;

        #pragma unroll
        for (int ko = 0; ko < 2; ko++){
            const uint32_t kb = (uint32_t)(ko * 32);
            uint32_t a_h[4][4], a_l[4][4], b_h[4][4], b_l[4][4];
            #pragma unroll
            for (int p = 0; p < 4; p++){
                uint32_t bd = sb + (uint32_t)((bRow0 + p*16) * 64) + ((kb + bC) ^ bSw);
                LDX4(b_h[p][0], b_h[p][1], b_h[p][2], b_h[p][3], bd + OFF_BH);
                if (NPROD == 3){
                    LDX4(b_l[p][0], b_l[p][1], b_l[p][2], b_l[p][3], bd + OFF_BL);
                }
            }
            #pragma unroll
            for (int mt = 0; mt < 4; mt++){
                uint32_t ad = sb + (uint32_t)((aRow0 + mt*16) * 64) + ((kb + aC) ^ aSw);
                LDX4(a_h[mt][0], a_h[mt][1], a_h[mt][2], a_h[mt][3], ad + OFF_AH);
                LDX4(a_l[mt][0], a_l[mt][1], a_l[mt][2], a_l[mt][3], ad + OFF_AL);
            }
            #pragma unroll
            for (int mt = 0; mt < 4; mt++)
                #pragma unroll
                for (int nt = 0; nt < 8; nt++){
                    uint32_t* bh = &b_h[nt >> 1][(nt & 1) * 2];
                    if (NPROD == 3){
                        uint32_t* bl = &b_l[nt >> 1][(nt & 1) * 2];
                        MMA_BF16(acc[mt][nt], a_h[mt], bh);
                        MMA_BF16(acc[mt][nt], a_h[mt], bl);
                        MMA_BF16(acc[mt][nt], a_l[mt], bh);
                    } else {
                        MMA_F16(acc[mt][nt], a_h[mt], bh);
                        MMA_F16(acc[mt][nt], a_l[mt], bh);
                    }
                }
        }
    }

    // ---- epilogue ----
    #pragma unroll
    for (int mt = 0; mt < 4; mt++){
        const int r0 = m0 + warpM + mt * 16 + (lane >> 2);
        const int r1 = r0 + 8;
        const float bm0 = biasM ? biasM[r0] : 0.f;
        const float bm1 = biasM ? biasM[r1] : 0.f;
        #pragma unroll
        for (int nt = 0; nt < 8; nt++){
            const int c = n0 + warpN + nt * 8 + ((lane & 3) << 1);
            float v0 = acc[mt][nt][0] * scale + bm0;
            float v1 = acc[mt][nt][1] * scale + bm0;
            float v2 = acc[mt][nt][2] * scale + bm1;
            float v3 = acc[mt][nt][3] * scale + bm1;
            if (biasN){
                float2 bn = *(const float2*)&biasN[c];
                v0 += bn.x; v1 += bn.y; v2 += bn.x; v3 += bn.y;
            }
            const size_t o0 = (size_t)r0 * ldc + c;
            const size_t o1 = (size_t)r1 * ldc + c;
            if (resid){
                float2 x0 = *(const float2*)&resid[o0];
                float2 x1 = *(const float2*)&resid[o1];
                v0 += x0.x; v1 += x0.y; v2 += x1.x; v3 += x1.y;
            }
            if (Cf){
                *(float2*)&Cf[o0] = make_float2(v0, v1);
                *(float2*)&Cf[o1] = make_float2(v2, v3);
            }
            if (Ch){
                uint32_t h01, l01, h23, l23;
                if (OUTF16){
                    split2pack_f16(v0, v1, h01, l01);
                    split2pack_f16(v2, v3, h23, l23);
                } else {
                    split2pack_bf(v0, v1, h01, l01);
                    split2pack_bf(v2, v3, h23, l23);
                }
                *(uint32_t*)&Ch[o0] = h01;  *(uint32_t*)&Cl[o0] = l01;
                *(uint32_t*)&Ch[o1] = h23;  *(uint32_t*)&Cl[o1] = l23;
            }
        }
    }
}

// ---------------- weight convert (bf16 pair) ----------------
__global__ void __launch_bounds__(256) wconv(const float* __restrict__ w0, const float* __restrict__ w1,
                                             const float* __restrict__ w2, const float* __restrict__ w3,
                                             u16* __restrict__ hi, u16* __restrict__ lo)
{
    int i = blockIdx.x * 256 + threadIdx.x;
    int w = i >> 16;
    int off = (i & 65535) * 4;
    const float* src = (w == 0) ? w0 : (w == 1) ? w1 : (w == 2) ? w2 : w3;
    float4 v = *(const float4*)(src + off);
    uint32_t h01, l01, h23, l23;
    split2pack_bf(v.x, v.y, h01, l01);
    split2pack_bf(v.z, v.w, h23, l23);
    size_t o = (size_t)w * CC * CC + off;
    *(uint32_t*)&hi[o]   = h01;  *(uint32_t*)&lo[o]   = l01;
    *(uint32_t*)&hi[o+2] = h23;  *(uint32_t*)&lo[o+2] = l23;
}

__global__ void bcat(const float* __restrict__ bq, const float* __restrict__ bk,
                     float* __restrict__ o)
{
    int i = blockIdx.x * 256 + threadIdx.x;
    if (i < 512) o[i] = bq[i];
    else if (i < 1024) o[i] = bk[i - 512];
}

// ---------------- GroupNorm stats ----------------
__global__ void __launch_bounds__(1024) gn_stats(const float* __restrict__ x, float* __restrict__ stats)
{
    int b = blockIdx.x >> 3, g = blockIdx.x & 7;
    const float* xp = x + ((size_t)b*CC + (size_t)g*CPG) * LLEN;
    const int n = CPG * LLEN;
    int tid = threadIdx.x;
    float s = 0.f, ss = 0.f;
    for (int i = tid; i < n; i += 1024){ float v = xp[i]; s += v; ss += v*v; }
    __shared__ float rs[32], rss[32];
    #pragma unroll
    for (int o = 16; o; o >>= 1){
        s  += __shfl_xor_sync(0xffffffffu, s,  o);
        ss += __shfl_xor_sync(0xffffffffu, ss, o);
    }
    if ((tid & 31) == 0){ rs[tid>>5] = s; rss[tid>>5] = ss; }
    __syncthreads();
    if (tid == 0){
        float t = 0.f, t2 = 0.f;
        #pragma unroll
        for (int i = 0; i < 32; i++){ t += rs[i]; t2 += rss[i]; }
        float mean = t / (float)n;
        float var  = t2 / (float)n - mean*mean;
        stats[blockIdx.x*2]   = mean;
        stats[blockIdx.x*2+1] = rsqrtf(var + 1e-6f);
    }
}

// ---------------- GroupNorm apply + transpose -> hT bf16 pair ----------------
__global__ void __launch_bounds__(256) gn_apply_t(const float* __restrict__ x,
                                                  const float* __restrict__ stats,
                                                  const float* __restrict__ gamma,
                                                  const float* __restrict__ beta,
                                                  u16* __restrict__ hTh,
                                                  u16* __restrict__ hTl)
{
    __shared__ float tile[64][33];
    int b = blockIdx.z, g = blockIdx.y, l0 = blockIdx.x * 32;
    float mean = stats[(b*NGRP+g)*2], inv = stats[(b*NGRP+g)*2+1];
    const float* xp = x + ((size_t)b*CC + (size_t)g*CPG) * LLEN;
    int tid = threadIdx.x;
    #pragma unroll
    for (int i = 0; i < 8; i++){
        int idx = tid + i*256; int c = idx >> 5, l = idx & 31;
        float v = xp[(size_t)c*LLEN + l0 + l];
        tile[c][l] = (v - mean) * inv * gamma[g*CPG + c] + beta[g*CPG + c];
    }
    __syncthreads();
    size_t base = (size_t)b * LLEN * CC;
    #pragma unroll
    for (int i = 0; i < 8; i++){
        int idx = tid + i*256; int l = idx >> 6, c = idx & 63;
        size_t o = base + (size_t)(l0 + l)*CC + g*CPG + c;
        split1_bf(tile[c][l], &hTh[o], &hTl[o]);
    }
}

// ---------------- row softmax over fp16 hi/lo pair, vectorized ----------------
__global__ void __launch_bounds__(256) softmax_kernel(u16* __restrict__ Sh,
                                                      u16* __restrict__ Sl)
{
    size_t ob = (size_t)blockIdx.x * LLEN;
    int tid = threadIdx.x;
    int base = tid * 8;
    uint4 hv = *(uint4*)&Sh[ob + base];
    uint4 lv = *(uint4*)&Sl[ob + base];
    float v[8];
    {
        uint32_t hw[4] = {hv.x, hv.y, hv.z, hv.w};
        uint32_t lw[4] = {lv.x, lv.y, lv.z, lv.w};
        #pragma unroll
        for (int i = 0; i < 4; i++){
            float2 h2 = __half22float2(*(__half2*)&hw[i]);
            float2 l2 = __half22float2(*(__half2*)&lw[i]);
            v[2*i]   = h2.x + l2.x;
            v[2*i+1] = h2.y + l2.y;
        }
    }
    float mx = -1e30f;
    #pragma unroll
    for (int i = 0; i < 8; i++) mx = fmaxf(mx, v[i]);
    __shared__ float rmax[8], rsum[8];
    #pragma unroll
    for (int o = 16; o; o >>= 1) mx = fmaxf(mx, __shfl_xor_sync(0xffffffffu, mx, o));
    if ((tid & 31) == 0) rmax[tid >> 5] = mx;
    __syncthreads();
    float m = rmax[0];
    #pragma unroll
    for (int i = 1; i < 8; i++) m = fmaxf(m, rmax[i]);
    float sm = 0.f;
    #pragma unroll
    for (int i = 0; i < 8; i++){ v[i] = __expf(v[i] - m); sm += v[i]; }
    #pragma unroll
    for (int o = 16; o; o >>= 1) sm += __shfl_xor_sync(0xffffffffu, sm, o);
    if ((tid & 31) == 0) rsum[tid >> 5] = sm;
    __syncthreads();
    float tot = 0.f;
    #pragma unroll
    for (int i = 0; i < 8; i++) tot += rsum[i];
    float inv = 1.f / tot;
    uint32_t ho[4], lo[4];
    #pragma unroll
    for (int i = 0; i < 4; i++)
        split2pack_f16(v[2*i] * inv, v[2*i+1] * inv, ho[i], lo[i]);
    *(uint4*)&Sh[ob + base] = make_uint4(ho[0], ho[1], ho[2], ho[3]);
    *(uint4*)&Sl[ob + base] = make_uint4(lo[0], lo[1], lo[2], lo[3]);
}

// ---------------- launch ----------------
extern "C" void kernel_launch(void* const* d_in, const int* in_sizes, int n_in,
                              void* d_out, int out_size)
{
    const float* x     = (const float*)d_in[0];
    const float* gamma = (const float*)d_in[1];
    const float* beta  = (const float*)d_in[2];
    const float* wq    = (const float*)d_in[3];
    const float* bq    = (const float*)d_in[4];
    const float* wk    = (const float*)d_in[5];
    const float* bk    = (const float*)d_in[6];
    const float* wv    = (const float*)d_in[7];
    const float* bv    = (const float*)d_in[8];
    const float* wo    = (const float*)d_in[9];
    const float* bo    = (const float*)d_in[10];
    float* out = (float*)d_out;

    u16 *hTh,*hTl,*qkh,*qkl,*vh,*vl,*h2h,*h2l,*sh,*sl,*wh,*wl;
    float *stats, *bqk;
    cudaGetSymbolAddress((void**)&hTh, g_hTh); cudaGetSymbolAddress((void**)&hTl, g_hTl);
    cudaGetSymbolAddress((void**)&qkh, g_qkh); cudaGetSymbolAddress((void**)&qkl, g_qkl);
    cudaGetSymbolAddress((void**)&vh,  g_vh);  cudaGetSymbolAddress((void**)&vl,  g_vl);
    cudaGetSymbolAddress((void**)&h2h, g_h2h); cudaGetSymbolAddress((void**)&h2l, g_h2l);
    cudaGetSymbolAddress((void**)&sh,  g_sh);  cudaGetSymbolAddress((void**)&sl,  g_sl);
    cudaGetSymbolAddress((void**)&wh,  g_wh);  cudaGetSymbolAddress((void**)&wl,  g_wl);
    cudaGetSymbolAddress((void**)&stats, g_stats);
    cudaGetSymbolAddress((void**)&bqk, g_bqk);

    const int DSM3 = NSTAGE*49152 + 128;
    const int DSM2 = NSTAGE*40960 + 128;
    cudaFuncSetAttribute(hmma_gemm<3,1>, cudaFuncAttributeMaxDynamicSharedMemorySize, DSM3);
    cudaFuncSetAttribute(hmma_gemm<3,0>, cudaFuncAttributeMaxDynamicSharedMemorySize, DSM3);
    cudaFuncSetAttribute(hmma_gemm<2,1>, cudaFuncAttributeMaxDynamicSharedMemorySize, DSM2);
    cudaFuncSetAttribute(hmma_gemm<2,0>, cudaFuncAttributeMaxDynamicSharedMemorySize, DSM2);

    const long LL  = (long)LLEN * LLEN;
    const long LQK = (long)LLEN * 1024;
    const float scl = 1.0f / sqrtf((float)CC);

    gn_stats<<<BB*NGRP, 1024>>>(x, stats);
    wconv<<<1024, 256>>>(wq, wk, wv, wo, wh, wl);
    bcat<<<4, 256>>>(bq, bk, bqk);
    gn_apply_t<<<dim3(LLEN/32, NGRP, BB), 256>>>(x, stats, gamma, beta, hTh, hTl);

    dim3 blk(256);
    // qk[l,n] = hT·w_qk + bqk  (bf16 3-prod in, fp16 pair out)  M=2048,N=1024,K=512
    hmma_gemm<3,1><<<dim3(8,8,BB), blk, DSM3>>>(hTh, hTl, wh, wl,
        CC, CC, CC, 1024, (long)CL, 0L, LQK, nullptr, qkh, qkl, nullptr, bqk, nullptr, 1.f);
    // v[c,l] = wv·hT + bv      (bf16 3-prod in, fp16 pair out)  M=512,N=2048,K=512
    hmma_gemm<3,1><<<dim3(16,2,BB), blk, DSM3>>>(wh + 2*CC*CC, wl + 2*CC*CC, hTh, hTl,
        CC, CC, CC, LLEN, 0L, (long)CL, (long)CL, nullptr, vh, vl, bv, nullptr, nullptr, 1.f);
    // S[i,j] = scl * q[i,:]·k[j,:]  (fp16 2-prod: A=q pair, B=k hi)  M=N=2048,K=512
    hmma_gemm<2,1><<<dim3(16,8,BB), blk, DSM2>>>(qkh, qkl, qkh + 512, qkl + 512,
        CC, 1024, 1024, LLEN, LQK, LQK, LL, nullptr, sh, sl, nullptr, nullptr, nullptr, scl);

    softmax_kernel<<<BB*LLEN, 256>>>(sh, sl);

    // h2T[i,c] = P[i,:]·v[c,:]  (fp16 2-prod: A=P pair, B=v hi; bf16 pair out)  M=2048,N=512,K=2048
    hmma_gemm<2,0><<<dim3(4,8,BB), blk, DSM2>>>(sh, sl, vh, vl,
        LLEN, LLEN, LLEN, CC, LL, (long)CL, (long)CL, nullptr, h2h, h2l, nullptr, nullptr, nullptr, 1.f);
    // out[c,l] = x + wo·h2T + bo  (bf16 3-prod, fp32 out)  M=512,N=2048,K=512
    hmma_gemm<3,0><<<dim3(16,2,BB), blk, DSM3>>>(wh + 3*CC*CC, wl + 3*CC*CC, h2h, h2l,
        CC, CC, CC, LLEN, 0L, (long)CL, (long)CL, out, nullptr, nullptr, bo, nullptr, x, 1.f);
}

// round 9
// speedup vs baseline: 2.4510x; 2.1050x over previous
#include <cuda_runtime.h>
#include <cuda_bf16.h>
#include <cuda_fp16.h>
#include <cstdint>
#include <math.h>

#define BB 8
#define CC 512
#define LLEN 2048
#define NGRP 8
#define CPG 64
#define CL (CC*LLEN)
typedef unsigned short u16;

// ---------------- scratch (single fp16 everywhere) ----------------
__device__ u16 g_hT[(size_t)BB*CL];                 // hT [B][L][C]
__device__ u16 g_qk[(size_t)BB*LLEN*1024];          // [B][L][1024] q|k
__device__ u16 g_v [(size_t)BB*CL];                 // v  [B][C][L]
__device__ u16 g_h2[(size_t)BB*CL];                 // h2T[B][L][C]
__device__ u16 g_s [(size_t)BB*LLEN*LLEN];          // S  [B][L][L]
__device__ u16 g_w [4*CC*CC];                       // wq,wk,wv,wo fp16
__device__ float g_bqk[1024];
__device__ float g_stats[BB*NGRP*2];

// ---------------- helpers ----------------
__device__ __forceinline__ uint32_t smem_u32(const void* p){
    uint32_t a;
    asm("{ .reg .u64 t; cvta.to.shared.u64 t, %1; cvt.u32.u64 %0, t; }" : "=r"(a) : "l"(p));
    return a;
}
__device__ __forceinline__ void cp16(uint32_t s, const void* g){
    asm volatile("cp.async.cg.shared.global [%0], [%1], 16;" :: "r"(s), "l"(g));
}
#define CP_COMMIT() asm volatile("cp.async.commit_group;" ::: "memory")
#define CP_WAIT2()  asm volatile("cp.async.wait_group 2;" ::: "memory")
#define CP_WAIT1()  asm volatile("cp.async.wait_group 1;" ::: "memory")
#define CP_WAIT0()  asm volatile("cp.async.wait_group 0;" ::: "memory")

#define LDX4(r0,r1,r2,r3,addr) \
    asm volatile("ldmatrix.sync.aligned.m8n8.x4.shared.b16 {%0,%1,%2,%3}, [%4];" \
        : "=r"(r0), "=r"(r1), "=r"(r2), "=r"(r3) : "r"(addr))

#define MMA_F16(d, a, b) \
    asm volatile("mma.sync.aligned.m16n8k16.row.col.f32.f16.f16.f32 " \
        "{%0,%1,%2,%3}, {%4,%5,%6,%7}, {%8,%9}, {%0,%1,%2,%3};" \
        : "+f"((d)[0]), "+f"((d)[1]), "+f"((d)[2]), "+f"((d)[3]) \
        : "r"((a)[0]), "r"((a)[1]), "r"((a)[2]), "r"((a)[3]), "r"((b)[0]), "r"((b)[1]))

__device__ __forceinline__ uint32_t pack_h2(float v0, float v1){
    __half2 h = __floats2half2_rn(v0, v1);
    return *(uint32_t*)&h;
}

// ---------------- fp16 HMMA GEMM: tile 256x128, 256 thr, warp 64x64, BK=64, 4-stage ----------------
// D[M,N] = scale*sum_k A[m][k]*B[n][k] (+biasM)(+biasN)(+resid)
#define OFF_A 0
#define OFF_B 32768
#define STG_B 49152
#define NSTAGE 4
#define DYN_SMEM (NSTAGE*STG_B + 128)

__global__ void __launch_bounds__(256, 1)
hmma_gemm(const u16* __restrict__ A, const u16* __restrict__ B,
          int K, int lda, int ldb, int ldc, long sA, long sB, long sC,
          float* __restrict__ Cf, u16* __restrict__ Ch,
          const float* __restrict__ biasM, const float* __restrict__ biasN,
          const float* __restrict__ resid, float scale)
{
    extern __shared__ char dsm[];
    const uint32_t sbase = (smem_u32(dsm) + 127u) & ~127u;
    const int tid = threadIdx.x, lane = tid & 31, wid = tid >> 5;
    const int warpM = (wid & 3) * 64, warpN = (wid >> 2) * 64;
    const int bz = blockIdx.z;
    A += (size_t)bz * sA;
    B += (size_t)bz * sB;
    if (Cf)    Cf    += (size_t)bz * sC;
    if (Ch)    Ch    += (size_t)bz * sC;
    if (resid) resid += (size_t)bz * sC;
    const int m0 = blockIdx.y * 256, n0 = blockIdx.x * 128;
    const int niter = K >> 6;

    // cp.async: 128B rows, seg = tid&7 (16B each), row_base = tid>>3 (0..31)
    const int c_row = tid >> 3, c_seg = tid & 7;
    const uint32_t c_cb = (uint32_t)(c_seg * 16);

    auto issue = [&](int kt){
        const int kk = kt * 64;
        const uint32_t sb = sbase + (kt & (NSTAGE-1)) * STG_B;
        #pragma unroll
        for (int j = 0; j < 8; j++){               // A: 256 rows
            const int row = c_row + j * 32;
            const uint32_t sw = (uint32_t)((row & 7) << 4);
            cp16(sb + OFF_A + row * 128 + (c_cb ^ sw),
                 A + (size_t)(m0 + row) * lda + kk + c_seg * 8);
        }
        #pragma unroll
        for (int j = 0; j < 4; j++){               // B: 128 rows
            const int row = c_row + j * 32;
            const uint32_t sw = (uint32_t)((row & 7) << 4);
            cp16(sb + OFF_B + row * 128 + (c_cb ^ sw),
                 B + (size_t)(n0 + row) * ldb + kk + c_seg * 8);
        }
        CP_COMMIT();
    };

    float acc[4][8][4];
    #pragma unroll
    for (int i = 0; i < 4; i++)
        #pragma unroll
        for (int j = 0; j < 8; j++)
            #pragma unroll
            for (int t = 0; t < 4; t++) acc[i][j][t] = 0.f;

    // ldmatrix lane addressing (128B rows, swizzle (row&7)<<4)
    const int aRow0 = warpM + (lane & 15);
    const uint32_t aSw = (uint32_t)((aRow0 & 7) << 4);
    const uint32_t aC  = (uint32_t)((lane >> 4) << 4);
    const int bRow0 = warpN + ((lane >> 4) << 3) + (lane & 7);
    const uint32_t bSw = (uint32_t)((bRow0 & 7) << 4);
    const uint32_t bC  = (uint32_t)(((lane >> 3) & 1) << 4);

    issue(0); issue(1); issue(2);

    for (int kt = 0; kt < niter; kt++){
        if (kt + 2 < niter)      CP_WAIT2();
        else if (kt + 1 < niter) CP_WAIT1();
        else                     CP_WAIT0();
        __syncthreads();
        if (kt + 3 < niter) issue(kt + 3);
        const uint32_t sb = sbase + (kt & (NSTAGE-1)) * STG_B;

        #pragma unroll
        for (int ko = 0; ko < 4; ko++){
            const uint32_t kb = (uint32_t)(ko * 32);
            uint32_t a_f[4][4], b_f[4][4];
            #pragma unroll
            for (int p = 0; p < 4; p++){
                uint32_t bd = sb + OFF_B + (uint32_t)((bRow0 + p*16) * 128) + ((kb + bC) ^ bSw);
                LDX4(b_f[p][0], b_f[p][1], b_f[p][2], b_f[p][3], bd);
            }
            #pragma unroll
            for (int mt = 0; mt < 4; mt++){
                uint32_t ad = sb + OFF_A + (uint32_t)((aRow0 + mt*16) * 128) + ((kb + aC) ^ aSw);
                LDX4(a_f[mt][0], a_f[mt][1], a_f[mt][2], a_f[mt][3], ad);
            }
            #pragma unroll
            for (int mt = 0; mt < 4; mt++)
                #pragma unroll
                for (int nt = 0; nt < 8; nt++)
                    MMA_F16(acc[mt][nt], a_f[mt], &b_f[nt >> 1][(nt & 1) * 2]);
        }
    }

    // ---- epilogue ----
    #pragma unroll
    for (int mt = 0; mt < 4; mt++){
        const int r0 = m0 + warpM + mt * 16 + (lane >> 2);
        const int r1 = r0 + 8;
        const float bm0 = biasM ? biasM[r0] : 0.f;
        const float bm1 = biasM ? biasM[r1] : 0.f;
        #pragma unroll
        for (int nt = 0; nt < 8; nt++){
            const int c = n0 + warpN + nt * 8 + ((lane & 3) << 1);
            float v0 = acc[mt][nt][0] * scale + bm0;
            float v1 = acc[mt][nt][1] * scale + bm0;
            float v2 = acc[mt][nt][2] * scale + bm1;
            float v3 = acc[mt][nt][3] * scale + bm1;
            if (biasN){
                float2 bn = *(const float2*)&biasN[c];
                v0 += bn.x; v1 += bn.y; v2 += bn.x; v3 += bn.y;
            }
            const size_t o0 = (size_t)r0 * ldc + c;
            const size_t o1 = (size_t)r1 * ldc + c;
            if (resid){
                float2 x0 = *(const float2*)&resid[o0];
                float2 x1 = *(const float2*)&resid[o1];
                v0 += x0.x; v1 += x0.y; v2 += x1.x; v3 += x1.y;
            }
            if (Cf){
                *(float2*)&Cf[o0] = make_float2(v0, v1);
                *(float2*)&Cf[o1] = make_float2(v2, v3);
            }
            if (Ch){
                *(uint32_t*)&Ch[o0] = pack_h2(v0, v1);
                *(uint32_t*)&Ch[o1] = pack_h2(v2, v3);
            }
        }
    }
}

// ---------------- weight convert (single fp16) ----------------
__global__ void __launch_bounds__(256) wconv(const float* __restrict__ w0, const float* __restrict__ w1,
                                             const float* __restrict__ w2, const float* __restrict__ w3,
                                             u16* __restrict__ wo)
{
    int i = blockIdx.x * 256 + threadIdx.x;
    int w = i >> 16;
    int off = (i & 65535) * 4;
    const float* src = (w == 0) ? w0 : (w == 1) ? w1 : (w == 2) ? w2 : w3;
    float4 v = *(const float4*)(src + off);
    size_t o = (size_t)w * CC * CC + off;
    *(uint32_t*)&wo[o]   = pack_h2(v.x, v.y);
    *(uint32_t*)&wo[o+2] = pack_h2(v.z, v.w);
}

__global__ void bcat(const float* __restrict__ bq, const float* __restrict__ bk,
                     float* __restrict__ o)
{
    int i = blockIdx.x * 256 + threadIdx.x;
    if (i < 512) o[i] = bq[i];
    else if (i < 1024) o[i] = bk[i - 512];
}

// ---------------- GroupNorm stats ----------------
__global__ void __launch_bounds__(1024) gn_stats(const float* __restrict__ x, float* __restrict__ stats)
{
    int b = blockIdx.x >> 3, g = blockIdx.x & 7;
    const float* xp = x + ((size_t)b*CC + (size_t)g*CPG) * LLEN;
    const int n = CPG * LLEN;
    int tid = threadIdx.x;
    float s = 0.f, ss = 0.f;
    for (int i = tid; i < n; i += 1024){ float v = xp[i]; s += v; ss += v*v; }
    __shared__ float rs[32], rss[32];
    #pragma unroll
    for (int o = 16; o; o >>= 1){
        s  += __shfl_xor_sync(0xffffffffu, s,  o);
        ss += __shfl_xor_sync(0xffffffffu, ss, o);
    }
    if ((tid & 31) == 0){ rs[tid>>5] = s; rss[tid>>5] = ss; }
    __syncthreads();
    if (tid == 0){
        float t = 0.f, t2 = 0.f;
        #pragma unroll
        for (int i = 0; i < 32; i++){ t += rs[i]; t2 += rss[i]; }
        float mean = t / (float)n;
        float var  = t2 / (float)n - mean*mean;
        stats[blockIdx.x*2]   = mean;
        stats[blockIdx.x*2+1] = rsqrtf(var + 1e-6f);
    }
}

// ---------------- GroupNorm apply + transpose -> hT fp16 ----------------
__global__ void __launch_bounds__(256) gn_apply_t(const float* __restrict__ x,
                                                  const float* __restrict__ stats,
                                                  const float* __restrict__ gamma,
                                                  const float* __restrict__ beta,
                                                  u16* __restrict__ hT)
{
    __shared__ float tile[64][33];
    int b = blockIdx.z, g = blockIdx.y, l0 = blockIdx.x * 32;
    float mean = stats[(b*NGRP+g)*2], inv = stats[(b*NGRP+g)*2+1];
    const float* xp = x + ((size_t)b*CC + (size_t)g*CPG) * LLEN;
    int tid = threadIdx.x;
    #pragma unroll
    for (int i = 0; i < 8; i++){
        int idx = tid + i*256; int c = idx >> 5, l = idx & 31;
        float v = xp[(size_t)c*LLEN + l0 + l];
        tile[c][l] = (v - mean) * inv * gamma[g*CPG + c] + beta[g*CPG + c];
    }
    __syncthreads();
    size_t base = (size_t)b * LLEN * CC;
    #pragma unroll
    for (int i = 0; i < 8; i++){
        int idx = tid + i*256; int l = idx >> 6, c = idx & 63;
        size_t o = base + (size_t)(l0 + l)*CC + g*CPG + c;
        hT[o] = __half_as_ushort(__float2half_rn(tile[c][l]));
    }
}

// ---------------- row softmax over fp16, in place ----------------
__global__ void __launch_bounds__(256) softmax_kernel(u16* __restrict__ S)
{
    size_t ob = (size_t)blockIdx.x * LLEN;
    int tid = threadIdx.x;
    int base = tid * 8;
    uint4 hv = *(uint4*)&S[ob + base];
    float v[8];
    {
        uint32_t hw[4] = {hv.x, hv.y, hv.z, hv.w};
        #pragma unroll
        for (int i = 0; i < 4; i++){
            float2 h2 = __half22float2(*(__half2*)&hw[i]);
            v[2*i] = h2.x; v[2*i+1] = h2.y;
        }
    }
    float mx = -1e30f;
    #pragma unroll
    for (int i = 0; i < 8; i++) mx = fmaxf(mx, v[i]);
    __shared__ float rmax[8], rsum[8];
    #pragma unroll
    for (int o = 16; o; o >>= 1) mx = fmaxf(mx, __shfl_xor_sync(0xffffffffu, mx, o));
    if ((tid & 31) == 0) rmax[tid >> 5] = mx;
    __syncthreads();
    float m = rmax[0];
    #pragma unroll
    for (int i = 1; i < 8; i++) m = fmaxf(m, rmax[i]);
    float sm = 0.f;
    #pragma unroll
    for (int i = 0; i < 8; i++){ v[i] = __expf(v[i] - m); sm += v[i]; }
    #pragma unroll
    for (int o = 16; o; o >>= 1) sm += __shfl_xor_sync(0xffffffffu, sm, o);
    if ((tid & 31) == 0) rsum[tid >> 5] = sm;
    __syncthreads();
    float tot = 0.f;
    #pragma unroll
    for (int i = 0; i < 8; i++) tot += rsum[i];
    float inv = 1.f / tot;
    uint32_t ho[4];
    #pragma unroll
    for (int i = 0; i < 4; i++)
        ho[i] = pack_h2(v[2*i] * inv, v[2*i+1] * inv);
    *(uint4*)&S[ob + base] = make_uint4(ho[0], ho[1], ho[2], ho[3]);
}

// ---------------- launch ----------------
extern "C" void kernel_launch(void* const* d_in, const int* in_sizes, int n_in,
                              void* d_out, int out_size)
{
    const float* x     = (const float*)d_in[0];
    const float* gamma = (const float*)d_in[1];
    const float* beta  = (const float*)d_in[2];
    const float* wq    = (const float*)d_in[3];
    const float* bq    = (const float*)d_in[4];
    const float* wk    = (const float*)d_in[5];
    const float* bk    = (const float*)d_in[6];
    const float* wv    = (const float*)d_in[7];
    const float* bv    = (const float*)d_in[8];
    const float* wo    = (const float*)d_in[9];
    const float* bo    = (const float*)d_in[10];
    float* out = (float*)d_out;

    u16 *hT,*qk,*v,*h2,*s,*w;
    float *stats, *bqk;
    cudaGetSymbolAddress((void**)&hT, g_hT);
    cudaGetSymbolAddress((void**)&qk, g_qk);
    cudaGetSymbolAddress((void**)&v,  g_v);
    cudaGetSymbolAddress((void**)&h2, g_h2);
    cudaGetSymbolAddress((void**)&s,  g_s);
    cudaGetSymbolAddress((void**)&w,  g_w);
    cudaGetSymbolAddress((void**)&stats, g_stats);
    cudaGetSymbolAddress((void**)&bqk, g_bqk);

    cudaFuncSetAttribute(hmma_gemm, cudaFuncAttributeMaxDynamicSharedMemorySize, DYN_SMEM);

    const long LL  = (long)LLEN * LLEN;
    const long LQK = (long)LLEN * 1024;
    const float scl = 1.0f / sqrtf((float)CC);

    gn_stats<<<BB*NGRP, 1024>>>(x, stats);
    wconv<<<1024, 256>>>(wq, wk, wv, wo, w);
    bcat<<<4, 256>>>(bq, bk, bqk);
    gn_apply_t<<<dim3(LLEN/32, NGRP, BB), 256>>>(x, stats, gamma, beta, hT);

    dim3 blk(256);
    // qk[l,n] = hT·w_qk + bqk     M=2048, N=1024, K=512
    hmma_gemm<<<dim3(8,8,BB), blk, DYN_SMEM>>>(hT, w,
        CC, CC, CC, 1024, (long)CL, 0L, LQK, nullptr, qk, nullptr, bqk, nullptr, 1.f);
    // v[c,l] = wv·hT + bv          M=512, N=2048, K=512
    hmma_gemm<<<dim3(16,2,BB), blk, DYN_SMEM>>>(w + 2*CC*CC, hT,
        CC, CC, CC, LLEN, 0L, (long)CL, (long)CL, nullptr, v, bv, nullptr, nullptr, 1.f);
    // S[i,j] = scl * q[i,:]·k[j,:] M=N=2048, K=512
    hmma_gemm<<<dim3(16,8,BB), blk, DYN_SMEM>>>(qk, qk + 512,
        CC, 1024, 1024, LLEN, LQK, LQK, LL, nullptr, s, nullptr, nullptr, nullptr, scl);

    softmax_kernel<<<BB*LLEN, 256>>>(s);

    // h2T[i,c] = P[i,:]·v[c,:]     M=2048, N=512, K=2048
    hmma_gemm<<<dim3(4,8,BB), blk, DYN_SMEM>>>(s, v,
        LLEN, LLEN, LLEN, CC, LL, (long)CL, (long)CL, nullptr, h2, nullptr, nullptr, nullptr, 1.f);
    // out[c,l] = x + wo·h2T + bo   M=512, N=2048, K=512
    hmma_gemm<<<dim3(16,2,BB), blk, DYN_SMEM>>>(w + 3*CC*CC, h2,
        CC, CC, CC, LLEN, 0L, (long)CL, (long)CL, out, nullptr, bo, nullptr, x, 1.f);
}

// round 10
// speedup vs baseline: 2.6010x; 1.0612x over previous
#include <cuda_runtime.h>
#include <cuda_bf16.h>
#include <cuda_fp16.h>
#include <cstdint>
#include <math.h>

#define BB 8
#define CC 512
#define LLEN 2048
#define NGRP 8
#define CPG 64
#define CL (CC*LLEN)
#define CC2 (CC*CC)
typedef unsigned short u16;

// ---------------- scratch ----------------
__device__ u16 g_hT[(size_t)BB*CL];          // hT [B][L][C] fp16
__device__ u16 g_h [(size_t)BB*CL];          // h  [B][C][L] fp16
__device__ u16 g_hp[(size_t)BB*CL];          // h'T = (M h)T [B][L][C]
__device__ u16 g_g [(size_t)BB*CL];          // gT = (P h)T [B][L][C]
__device__ u16 g_s [(size_t)BB*LLEN*LLEN];   // S [B][L][L]
__device__ u16 g_wA[2*CC2];                  // {wqT, wo} fp16
__device__ u16 g_wB[2*CC2];                  // {wkT, wvT} fp16
__device__ u16 g_wM[2*CC2];                  // {M=WqT*Wk, Wov=Wo*Wv} fp16
__device__ float g_u [CC];                   // WkT * bq
__device__ float g_bp[CC];                   // Wo*bv + bo
__device__ float g_cv[BB*LLEN];              // c_j per (b,j), pre-scaled
__device__ float g_stats[BB*NGRP*2];

// ---------------- helpers ----------------
__device__ __forceinline__ uint32_t smem_u32(const void* p){
    uint32_t a;
    asm("{ .reg .u64 t; cvta.to.shared.u64 t, %1; cvt.u32.u64 %0, t; }" : "=r"(a) : "l"(p));
    return a;
}
__device__ __forceinline__ void cp16(uint32_t s, const void* g){
    asm volatile("cp.async.cg.shared.global [%0], [%1], 16;" :: "r"(s), "l"(g));
}
#define CP_COMMIT() asm volatile("cp.async.commit_group;" ::: "memory")
#define CP_WAIT2()  asm volatile("cp.async.wait_group 2;" ::: "memory")
#define CP_WAIT1()  asm volatile("cp.async.wait_group 1;" ::: "memory")
#define CP_WAIT0()  asm volatile("cp.async.wait_group 0;" ::: "memory")

#define LDX4(r0,r1,r2,r3,addr) \
    asm volatile("ldmatrix.sync.aligned.m8n8.x4.shared.b16 {%0,%1,%2,%3}, [%4];" \
        : "=r"(r0), "=r"(r1), "=r"(r2), "=r"(r3) : "r"(addr))

#define MMA_F16(d, a, b) \
    asm volatile("mma.sync.aligned.m16n8k16.row.col.f32.f16.f16.f32 " \
        "{%0,%1,%2,%3}, {%4,%5,%6,%7}, {%8,%9}, {%0,%1,%2,%3};" \
        : "+f"((d)[0]), "+f"((d)[1]), "+f"((d)[2]), "+f"((d)[3]) \
        : "r"((a)[0]), "r"((a)[1]), "r"((a)[2]), "r"((a)[3]), "r"((b)[0]), "r"((b)[1]))

__device__ __forceinline__ uint32_t pack_h2(float v0, float v1){
    __half2 h = __floats2half2_rn(v0, v1);
    return *(uint32_t*)&h;
}
__device__ __forceinline__ float h2f(u16 v){ return __half2float(__ushort_as_half(v)); }

// ---------------- fp16 HMMA GEMM: tile 256x128, 256 thr, warp 64x64, BK=64, 4-stage ----------------
#define OFF_A 0
#define OFF_B 32768
#define STG_B 49152
#define NSTAGE 4
#define DYN_SMEM (NSTAGE*STG_B + 128)

__global__ void __launch_bounds__(256, 1)
hmma_gemm(const u16* __restrict__ A, const u16* __restrict__ B,
          int K, int lda, int ldb, int ldc, long sA, long sB, long sC,
          float* __restrict__ Cf, u16* __restrict__ Ch,
          const float* __restrict__ biasM, const float* __restrict__ biasN, long sBN,
          const float* __restrict__ resid, float scale)
{
    extern __shared__ char dsm[];
    const uint32_t sbase = (smem_u32(dsm) + 127u) & ~127u;
    const int tid = threadIdx.x, lane = tid & 31, wid = tid >> 5;
    const int warpM = (wid & 3) * 64, warpN = (wid >> 2) * 64;
    const int bz = blockIdx.z;
    A += (size_t)bz * sA;
    B += (size_t)bz * sB;
    if (Cf)    Cf    += (size_t)bz * sC;
    if (Ch)    Ch    += (size_t)bz * sC;
    if (resid) resid += (size_t)bz * sC;
    if (biasN) biasN += (size_t)bz * sBN;
    const int m0 = blockIdx.y * 256, n0 = blockIdx.x * 128;
    const int niter = K >> 6;

    const int c_row = tid >> 3, c_seg = tid & 7;
    const uint32_t c_cb = (uint32_t)(c_seg * 16);

    auto issue = [&](int kt){
        const int kk = kt * 64;
        const uint32_t sb = sbase + (kt & (NSTAGE-1)) * STG_B;
        #pragma unroll
        for (int j = 0; j < 8; j++){
            const int row = c_row + j * 32;
            const uint32_t sw = (uint32_t)((row & 7) << 4);
            cp16(sb + OFF_A + row * 128 + (c_cb ^ sw),
                 A + (size_t)(m0 + row) * lda + kk + c_seg * 8);
        }
        #pragma unroll
        for (int j = 0; j < 4; j++){
            const int row = c_row + j * 32;
            const uint32_t sw = (uint32_t)((row & 7) << 4);
            cp16(sb + OFF_B + row * 128 + (c_cb ^ sw),
                 B + (size_t)(n0 + row) * ldb + kk + c_seg * 8);
        }
        CP_COMMIT();
    };

    float acc[4][8][4];
    #pragma unroll
    for (int i = 0; i < 4; i++)
        #pragma unroll
        for (int j = 0; j < 8; j++)
            #pragma unroll
            for (int t = 0; t < 4; t++) acc[i][j][t] = 0.f;

    const int aRow0 = warpM + (lane & 15);
    const uint32_t aSw = (uint32_t)((aRow0 & 7) << 4);
    const uint32_t aC  = (uint32_t)((lane >> 4) << 4);
    const int bRow0 = warpN + ((lane >> 4) << 3) + (lane & 7);
    const uint32_t bSw = (uint32_t)((bRow0 & 7) << 4);
    const uint32_t bC  = (uint32_t)(((lane >> 3) & 1) << 4);

    issue(0); issue(1); issue(2);

    for (int kt = 0; kt < niter; kt++){
        if (kt + 2 < niter)      CP_WAIT2();
        else if (kt + 1 < niter) CP_WAIT1();
        else                     CP_WAIT0();
        __syncthreads();
        if (kt + 3 < niter) issue(kt + 3);
        const uint32_t sb = sbase + (kt & (NSTAGE-1)) * STG_B;

        #pragma unroll
        for (int ko = 0; ko < 4; ko++){
            const uint32_t kb = (uint32_t)(ko * 32);
            uint32_t a_f[4][4], b_f[4][4];
            #pragma unroll
            for (int p = 0; p < 4; p++){
                uint32_t bd = sb + OFF_B + (uint32_t)((bRow0 + p*16) * 128) + ((kb + bC) ^ bSw);
                LDX4(b_f[p][0], b_f[p][1], b_f[p][2], b_f[p][3], bd);
            }
            #pragma unroll
            for (int mt = 0; mt < 4; mt++){
                uint32_t ad = sb + OFF_A + (uint32_t)((aRow0 + mt*16) * 128) + ((kb + aC) ^ aSw);
                LDX4(a_f[mt][0], a_f[mt][1], a_f[mt][2], a_f[mt][3], ad);
            }
            #pragma unroll
            for (int mt = 0; mt < 4; mt++)
                #pragma unroll
                for (int nt = 0; nt < 8; nt++)
                    MMA_F16(acc[mt][nt], a_f[mt], &b_f[nt >> 1][(nt & 1) * 2]);
        }
    }

    // ---- epilogue ----
    #pragma unroll
    for (int mt = 0; mt < 4; mt++){
        const int r0 = m0 + warpM + mt * 16 + (lane >> 2);
        const int r1 = r0 + 8;
        const float bm0 = biasM ? biasM[r0] : 0.f;
        const float bm1 = biasM ? biasM[r1] : 0.f;
        #pragma unroll
        for (int nt = 0; nt < 8; nt++){
            const int c = n0 + warpN + nt * 8 + ((lane & 3) << 1);
            float v0 = acc[mt][nt][0] * scale + bm0;
            float v1 = acc[mt][nt][1] * scale + bm0;
            float v2 = acc[mt][nt][2] * scale + bm1;
            float v3 = acc[mt][nt][3] * scale + bm1;
            if (biasN){
                float2 bn = *(const float2*)&biasN[c];
                v0 += bn.x; v1 += bn.y; v2 += bn.x; v3 += bn.y;
            }
            const size_t o0 = (size_t)r0 * ldc + c;
            const size_t o1 = (size_t)r1 * ldc + c;
            if (resid){
                float2 x0 = *(const float2*)&resid[o0];
                float2 x1 = *(const float2*)&resid[o1];
                v0 += x0.x; v1 += x0.y; v2 += x1.x; v3 += x1.y;
            }
            if (Cf){
                *(float2*)&Cf[o0] = make_float2(v0, v1);
                *(float2*)&Cf[o1] = make_float2(v2, v3);
            }
            if (Ch){
                *(uint32_t*)&Ch[o0] = pack_h2(v0, v1);
                *(uint32_t*)&Ch[o1] = pack_h2(v2, v3);
            }
        }
    }
}

// ---------------- weight convert/transpose ----------------
// z: 0 wq->wA[0] (T)   1 wk->wB[0] (T)   2 wv->wB[CC2] (T)   3 wo->wA[CC2] (direct)
__global__ void __launch_bounds__(256) wconvT(const float* __restrict__ wq, const float* __restrict__ wk,
                                              const float* __restrict__ wv, const float* __restrict__ wo_,
                                              u16* __restrict__ wA, u16* __restrict__ wB)
{
    __shared__ float t[32][33];
    int z = blockIdx.z;
    int r0 = blockIdx.y * 32, c0 = blockIdx.x * 32;
    const float* src = (z==0) ? wq : (z==1) ? wk : (z==2) ? wv : wo_;
    u16* dst = (z==0) ? wA : (z==1) ? wB : (z==2) ? (wB + CC2) : (wA + CC2);
    int tx = threadIdx.x & 31, ty = threadIdx.x >> 5;   // 32x8
    if (z < 3){
        #pragma unroll
        for (int i = 0; i < 4; i++)
            t[ty + 8*i][tx] = src[(size_t)(r0 + ty + 8*i)*CC + c0 + tx];
        __syncthreads();
        #pragma unroll
        for (int i = 0; i < 4; i++)
            dst[(size_t)(c0 + ty + 8*i)*CC + r0 + tx] =
                __half_as_ushort(__float2half_rn(t[tx][ty + 8*i]));
    } else {
        #pragma unroll
        for (int i = 0; i < 4; i++){
            size_t o = (size_t)(r0 + ty + 8*i)*CC + c0 + tx;
            dst[o] = __half_as_ushort(__float2half_rn(src[o]));
        }
    }
}

// ---------------- small vectors: u = WkT bq ; bp = Wo bv + bo ----------------
__global__ void __launch_bounds__(128) smallvec(const u16* __restrict__ wkT, const u16* __restrict__ wo16,
                                                const float* __restrict__ bq, const float* __restrict__ bv,
                                                const float* __restrict__ bo,
                                                float* __restrict__ u, float* __restrict__ bp)
{
    int gw = (blockIdx.x * 128 + threadIdx.x) >> 5;
    int lane = threadIdx.x & 31;
    float s = 0.f;
    if (gw < 512){
        for (int o = lane; o < 512; o += 32) s += h2f(wkT[(size_t)gw*512 + o]) * bq[o];
        #pragma unroll
        for (int k = 16; k; k >>= 1) s += __shfl_xor_sync(0xffffffffu, s, k);
        if (!lane) u[gw] = s;
    } else {
        int o = gw - 512;
        for (int c = lane; c < 512; c += 32) s += h2f(wo16[(size_t)o*512 + c]) * bv[c];
        #pragma unroll
        for (int k = 16; k; k >>= 1) s += __shfl_xor_sync(0xffffffffu, s, k);
        if (!lane) bp[o] = bo[o] + s;
    }
}

// ---------------- cvec: c[b][j] = scl * hT[b][j]·u ----------------
__global__ void __launch_bounds__(256) cvec(const u16* __restrict__ hT, const float* __restrict__ u,
                                            float* __restrict__ cv, float scl)
{
    int gw = (blockIdx.x * 256 + threadIdx.x) >> 5;   // 0..16383
    int lane = threadIdx.x & 31;
    const u16* row = hT + (size_t)gw * 512;
    float s = 0.f;
    for (int c = lane; c < 512; c += 32) s += h2f(row[c]) * u[c];
    #pragma unroll
    for (int k = 16; k; k >>= 1) s += __shfl_xor_sync(0xffffffffu, s, k);
    if (!lane) cv[gw] = s * scl;
}

// ---------------- GroupNorm stats ----------------
__global__ void __launch_bounds__(1024) gn_stats(const float* __restrict__ x, float* __restrict__ stats)
{
    int b = blockIdx.x >> 3, g = blockIdx.x & 7;
    const float* xp = x + ((size_t)b*CC + (size_t)g*CPG) * LLEN;
    const int n = CPG * LLEN;
    int tid = threadIdx.x;
    float s = 0.f, ss = 0.f;
    for (int i = tid; i < n; i += 1024){ float v = xp[i]; s += v; ss += v*v; }
    __shared__ float rs[32], rss[32];
    #pragma unroll
    for (int o = 16; o; o >>= 1){
        s  += __shfl_xor_sync(0xffffffffu, s,  o);
        ss += __shfl_xor_sync(0xffffffffu, ss, o);
    }
    if ((tid & 31) == 0){ rs[tid>>5] = s; rss[tid>>5] = ss; }
    __syncthreads();
    if (tid == 0){
        float t = 0.f, t2 = 0.f;
        #pragma unroll
        for (int i = 0; i < 32; i++){ t += rs[i]; t2 += rss[i]; }
        float mean = t / (float)n;
        float var  = t2 / (float)n - mean*mean;
        stats[blockIdx.x*2]   = mean;
        stats[blockIdx.x*2+1] = rsqrtf(var + 1e-6f);
    }
}

// ---------------- GroupNorm apply -> hT [L][C] and h [C][L], both fp16 ----------------
__global__ void __launch_bounds__(256) gn_apply_t(const float* __restrict__ x,
                                                  const float* __restrict__ stats,
                                                  const float* __restrict__ gamma,
                                                  const float* __restrict__ beta,
                                                  u16* __restrict__ hT, u16* __restrict__ h)
{
    __shared__ float tile[64][33];
    int b = blockIdx.z, g = blockIdx.y, l0 = blockIdx.x * 32;
    float mean = stats[(b*NGRP+g)*2], inv = stats[(b*NGRP+g)*2+1];
    const float* xp = x + ((size_t)b*CC + (size_t)g*CPG) * LLEN;
    u16* hp = h + ((size_t)b*CC + (size_t)g*CPG) * LLEN;
    int tid = threadIdx.x;
    #pragma unroll
    for (int i = 0; i < 8; i++){
        int idx = tid + i*256; int c = idx >> 5, l = idx & 31;
        float v = xp[(size_t)c*LLEN + l0 + l];
        float r = (v - mean) * inv * gamma[g*CPG + c] + beta[g*CPG + c];
        tile[c][l] = r;
        hp[(size_t)c*LLEN + l0 + l] = __half_as_ushort(__float2half_rn(r));
    }
    __syncthreads();
    size_t base = (size_t)b * LLEN * CC;
    #pragma unroll
    for (int i = 0; i < 8; i++){
        int idx = tid + i*256; int l = idx >> 6, c = idx & 63;
        size_t o = base + (size_t)(l0 + l)*CC + g*CPG + c;
        hT[o] = __half_as_ushort(__float2half_rn(tile[c][l]));
    }
}

// ---------------- row softmax over fp16, in place ----------------
__global__ void __launch_bounds__(256) softmax_kernel(u16* __restrict__ S)
{
    size_t ob = (size_t)blockIdx.x * LLEN;
    int tid = threadIdx.x;
    int base = tid * 8;
    uint4 hv = *(uint4*)&S[ob + base];
    float v[8];
    {
        uint32_t hw[4] = {hv.x, hv.y, hv.z, hv.w};
        #pragma unroll
        for (int i = 0; i < 4; i++){
            float2 h2 = __half22float2(*(__half2*)&hw[i]);
            v[2*i] = h2.x; v[2*i+1] = h2.y;
        }
    }
    float mx = -1e30f;
    #pragma unroll
    for (int i = 0; i < 8; i++) mx = fmaxf(mx, v[i]);
    __shared__ float rmax[8], rsum[8];
    #pragma unroll
    for (int o = 16; o; o >>= 1) mx = fmaxf(mx, __shfl_xor_sync(0xffffffffu, mx, o));
    if ((tid & 31) == 0) rmax[tid >> 5] = mx;
    __syncthreads();
    float m = rmax[0];
    #pragma unroll
    for (int i = 1; i < 8; i++) m = fmaxf(m, rmax[i]);
    float sm = 0.f;
    #pragma unroll
    for (int i = 0; i < 8; i++){ v[i] = __expf(v[i] - m); sm += v[i]; }
    #pragma unroll
    for (int o = 16; o; o >>= 1) sm += __shfl_xor_sync(0xffffffffu, sm, o);
    if ((tid & 31) == 0) rsum[tid >> 5] = sm;
    __syncthreads();
    float tot = 0.f;
    #pragma unroll
    for (int i = 0; i < 8; i++) tot += rsum[i];
    float inv = 1.f / tot;
    uint32_t ho[4];
    #pragma unroll
    for (int i = 0; i < 4; i++)
        ho[i] = pack_h2(v[2*i] * inv, v[2*i+1] * inv);
    *(uint4*)&S[ob + base] = make_uint4(ho[0], ho[1], ho[2], ho[3]);
}

// ---------------- launch ----------------
extern "C" void kernel_launch(void* const* d_in, const int* in_sizes, int n_in,
                              void* d_out, int out_size)
{
    const float* x     = (const float*)d_in[0];
    const float* gamma = (const float*)d_in[1];
    const float* beta  = (const float*)d_in[2];
    const float* wq    = (const float*)d_in[3];
    const float* bq    = (const float*)d_in[4];
    const float* wk    = (const float*)d_in[5];
    // bk (d_in[6]) cancels inside softmax — unused
    const float* wv    = (const float*)d_in[7];
    const float* bv    = (const float*)d_in[8];
    const float* wo    = (const float*)d_in[9];
    const float* bo    = (const float*)d_in[10];
    float* out = (float*)d_out;

    u16 *hT,*h,*hp,*g,*s,*wA,*wB,*wM;
    float *stats, *u, *bp, *cv;
    cudaGetSymbolAddress((void**)&hT, g_hT);
    cudaGetSymbolAddress((void**)&h,  g_h);
    cudaGetSymbolAddress((void**)&hp, g_hp);
    cudaGetSymbolAddress((void**)&g,  g_g);
    cudaGetSymbolAddress((void**)&s,  g_s);
    cudaGetSymbolAddress((void**)&wA, g_wA);
    cudaGetSymbolAddress((void**)&wB, g_wB);
    cudaGetSymbolAddress((void**)&wM, g_wM);
    cudaGetSymbolAddress((void**)&stats, g_stats);
    cudaGetSymbolAddress((void**)&u,  g_u);
    cudaGetSymbolAddress((void**)&bp, g_bp);
    cudaGetSymbolAddress((void**)&cv, g_cv);

    cudaFuncSetAttribute(hmma_gemm, cudaFuncAttributeMaxDynamicSharedMemorySize, DYN_SMEM);

    const long LL = (long)LLEN * LLEN;
    const float scl = 1.0f / sqrtf((float)CC);

    gn_stats<<<BB*NGRP, 1024>>>(x, stats);
    wconvT<<<dim3(16,16,4), 256>>>(wq, wk, wv, wo, wA, wB);
    // {M, Wov} = batched 512x512x512: z=0: wqT*wkT^T ; z=1: wo*wvT^T
    hmma_gemm<<<dim3(4,2,2), 256, DYN_SMEM>>>(wA, wB,
        CC, CC, CC, CC, (long)CC2, (long)CC2, (long)CC2,
        nullptr, wM, nullptr, nullptr, 0L, nullptr, 1.f);
    smallvec<<<256, 128>>>(wB, wA + CC2, bq, bv, bo, u, bp);
    gn_apply_t<<<dim3(LLEN/32, NGRP, BB), 256>>>(x, stats, gamma, beta, hT, h);
    cvec<<<2048, 256>>>(hT, u, cv, scl);

    dim3 blk(256);
    // h'T[j,c] = sum_c' hT[j,c'] M[c,c']       M=2048, N=512, K=512
    hmma_gemm<<<dim3(4,8,BB), blk, DYN_SMEM>>>(hT, wM,
        CC, CC, CC, CC, (long)CL, 0L, (long)CL,
        nullptr, hp, nullptr, nullptr, 0L, nullptr, 1.f);
    // S[i,j] = scl*(hT[i]·h'T[j]) + cv[b][j]   M=N=2048, K=512
    hmma_gemm<<<dim3(16,8,BB), blk, DYN_SMEM>>>(hT, hp,
        CC, CC, CC, LLEN, (long)CL, (long)CL, LL,
        nullptr, s, nullptr, cv, (long)LLEN, nullptr, scl);

    softmax_kernel<<<BB*LLEN, 256>>>(s);

    // gT[i,c] = sum_j P[i,j] h[c,j]            M=2048, N=512, K=2048
    hmma_gemm<<<dim3(4,8,BB), blk, DYN_SMEM>>>(s, h,
        LLEN, LLEN, LLEN, CC, LL, (long)CL, (long)CL,
        nullptr, g, nullptr, nullptr, 0L, nullptr, 1.f);
    // out[o,l] = x + sum_c' Wov[o,c'] gT[l,c'] + bp[o]   M=512, N=2048, K=512
    hmma_gemm<<<dim3(16,2,BB), blk, DYN_SMEM>>>(wM + CC2, g,
        CC, CC, CC, LLEN, 0L, (long)CL, (long)CL,
        out, nullptr, bp, nullptr, 0L, x, 1.f);
}

// round 11
// speedup vs baseline: 2.8650x; 1.1015x over previous
#include <cuda_runtime.h>
#include <cuda_bf16.h>
#include <cuda_fp16.h>
#include <cstdint>
#include <math.h>

#define BB 8
#define CC 512
#define LLEN 2048
#define NGRP 8
#define CPG 64
#define CL (CC*LLEN)
#define CC2 (CC*CC)
typedef unsigned short u16;

// ---------------- scratch ----------------
__device__ u16 g_hT[(size_t)BB*CL];          // hT [B][L][C] fp16
__device__ u16 g_h [(size_t)BB*CL];          // h  [B][C][L] fp16
__device__ u16 g_hp[(size_t)BB*CL];          // h'T = (M h)T [B][L][C]
__device__ u16 g_g [(size_t)BB*CL];          // gT = (P h)T [B][L][C]
__device__ u16 g_s [(size_t)BB*LLEN*LLEN];   // S [B][L][L]
__device__ u16 g_wA[2*CC2];                  // {wqT, wo} fp16
__device__ u16 g_wB[2*CC2];                  // {wkT, wvT} fp16
__device__ u16 g_wM[2*CC2];                  // {M=WqT*Wk, Wov=Wo*Wv} fp16
__device__ float g_u [CC];                   // WkT * bq
__device__ float g_bp[CC];                   // Wo*bv + bo
__device__ float g_cv[BB*LLEN];              // c_j per (b,j), pre-scaled
__device__ float2 g_part[512];               // GN partial (sum, sumsq)

// ---------------- helpers ----------------
__device__ __forceinline__ uint32_t smem_u32(const void* p){
    uint32_t a;
    asm("{ .reg .u64 t; cvta.to.shared.u64 t, %1; cvt.u32.u64 %0, t; }" : "=r"(a) : "l"(p));
    return a;
}
__device__ __forceinline__ void cp16(uint32_t s, const void* g){
    asm volatile("cp.async.cg.shared.global [%0], [%1], 16;" :: "r"(s), "l"(g));
}
#define CP_COMMIT() asm volatile("cp.async.commit_group;" ::: "memory")
#define CP_WAIT1()  asm volatile("cp.async.wait_group 1;" ::: "memory")
#define CP_WAIT0()  asm volatile("cp.async.wait_group 0;" ::: "memory")

#define LDX4(r0,r1,r2,r3,addr) \
    asm volatile("ldmatrix.sync.aligned.m8n8.x4.shared.b16 {%0,%1,%2,%3}, [%4];" \
        : "=r"(r0), "=r"(r1), "=r"(r2), "=r"(r3) : "r"(addr))

#define MMA_F16(d, a, b) \
    asm volatile("mma.sync.aligned.m16n8k16.row.col.f32.f16.f16.f32 " \
        "{%0,%1,%2,%3}, {%4,%5,%6,%7}, {%8,%9}, {%0,%1,%2,%3};" \
        : "+f"((d)[0]), "+f"((d)[1]), "+f"((d)[2]), "+f"((d)[3]) \
        : "r"((a)[0]), "r"((a)[1]), "r"((a)[2]), "r"((a)[3]), "r"((b)[0]), "r"((b)[1]))

__device__ __forceinline__ uint32_t pack_h2(float v0, float v1){
    __half2 h = __floats2half2_rn(v0, v1);
    return *(uint32_t*)&h;
}
__device__ __forceinline__ float h2f(u16 v){ return __half2float(__ushort_as_half(v)); }

// ---------------- fp16 HMMA GEMM: tile 128x128, 128 thr, warp 64x64, BK=64, 3-stage, 2 CTA/SM ----------------
#define OFF_A 0
#define OFF_B 16384
#define STG_B 32768
#define NSTAGE 3
#define DYN_SMEM (NSTAGE*STG_B + 128)

__global__ void __launch_bounds__(128, 2)
hmma_gemm(const u16* __restrict__ A, const u16* __restrict__ B,
          int K, int lda, int ldb, int ldc, long sA, long sB, long sC,
          float* __restrict__ Cf, u16* __restrict__ Ch,
          const float* __restrict__ biasM, const float* __restrict__ biasN, long sBN,
          const float* __restrict__ resid, float scale)
{
    extern __shared__ char dsm[];
    const uint32_t sbase = (smem_u32(dsm) + 127u) & ~127u;
    const int tid = threadIdx.x, lane = tid & 31, wid = tid >> 5;
    const int warpM = (wid & 1) * 64, warpN = (wid >> 1) * 64;
    const int bz = blockIdx.z;
    A += (size_t)bz * sA;
    B += (size_t)bz * sB;
    if (Cf)    Cf    += (size_t)bz * sC;
    if (Ch)    Ch    += (size_t)bz * sC;
    if (resid) resid += (size_t)bz * sC;
    if (biasN) biasN += (size_t)bz * sBN;
    const int m0 = blockIdx.y * 128, n0 = blockIdx.x * 128;
    const int niter = K >> 6;

    const int c_row = tid >> 3, c_seg = tid & 7;   // 16 rows x 8 segs
    const uint32_t c_cb = (uint32_t)(c_seg * 16);

    auto issue = [&](int kt){
        const int kk = kt * 64;
        const uint32_t sb = sbase + (kt % NSTAGE) * STG_B;
        #pragma unroll
        for (int j = 0; j < 8; j++){               // A: 128 rows
            const int row = c_row + j * 16;
            const uint32_t sw = (uint32_t)((row & 7) << 4);
            cp16(sb + OFF_A + row * 128 + (c_cb ^ sw),
                 A + (size_t)(m0 + row) * lda + kk + c_seg * 8);
        }
        #pragma unroll
        for (int j = 0; j < 8; j++){               // B: 128 rows
            const int row = c_row + j * 16;
            const uint32_t sw = (uint32_t)((row & 7) << 4);
            cp16(sb + OFF_B + row * 128 + (c_cb ^ sw),
                 B + (size_t)(n0 + row) * ldb + kk + c_seg * 8);
        }
        CP_COMMIT();
    };

    float acc[4][8][4];
    #pragma unroll
    for (int i = 0; i < 4; i++)
        #pragma unroll
        for (int j = 0; j < 8; j++)
            #pragma unroll
            for (int t = 0; t < 4; t++) acc[i][j][t] = 0.f;

    const int aRow0 = warpM + (lane & 15);
    const uint32_t aSw = (uint32_t)((aRow0 & 7) << 4);
    const uint32_t aC  = (uint32_t)((lane >> 4) << 4);
    const int bRow0 = warpN + ((lane >> 4) << 3) + (lane & 7);
    const uint32_t bSw = (uint32_t)((bRow0 & 7) << 4);
    const uint32_t bC  = (uint32_t)(((lane >> 3) & 1) << 4);

    issue(0); if (niter > 1) issue(1);

    for (int kt = 0; kt < niter; kt++){
        if (kt + 1 < niter) CP_WAIT1(); else CP_WAIT0();
        __syncthreads();
        if (kt + 2 < niter) issue(kt + 2);
        const uint32_t sb = sbase + (kt % NSTAGE) * STG_B;

        #pragma unroll
        for (int ko = 0; ko < 4; ko++){
            const uint32_t kb = (uint32_t)(ko * 32);
            uint32_t a_f[4][4], b_f[4][4];
            #pragma unroll
            for (int p = 0; p < 4; p++){
                uint32_t bd = sb + OFF_B + (uint32_t)((bRow0 + p*16) * 128) + ((kb + bC) ^ bSw);
                LDX4(b_f[p][0], b_f[p][1], b_f[p][2], b_f[p][3], bd);
            }
            #pragma unroll
            for (int mt = 0; mt < 4; mt++){
                uint32_t ad = sb + OFF_A + (uint32_t)((aRow0 + (mt&1)*16 + (mt>>1)*32) * 128) + ((kb + aC) ^ aSw);
                LDX4(a_f[mt][0], a_f[mt][1], a_f[mt][2], a_f[mt][3], ad);
            }
            #pragma unroll
            for (int mt = 0; mt < 4; mt++)
                #pragma unroll
                for (int nt = 0; nt < 8; nt++)
                    MMA_F16(acc[mt][nt], a_f[mt], &b_f[nt >> 1][(nt & 1) * 2]);
        }
        __syncthreads();
    }

    // ---- epilogue ----
    #pragma unroll
    for (int mt = 0; mt < 4; mt++){
        const int mrow = (mt&1)*16 + (mt>>1)*32;
        const int r0 = m0 + warpM + mrow + (lane >> 2);
        const int r1 = r0 + 8;
        const float bm0 = biasM ? biasM[r0] : 0.f;
        const float bm1 = biasM ? biasM[r1] : 0.f;
        #pragma unroll
        for (int nt = 0; nt < 8; nt++){
            const int c = n0 + warpN + nt * 8 + ((lane & 3) << 1);
            float v0 = acc[mt][nt][0] * scale + bm0;
            float v1 = acc[mt][nt][1] * scale + bm0;
            float v2 = acc[mt][nt][2] * scale + bm1;
            float v3 = acc[mt][nt][3] * scale + bm1;
            if (biasN){
                float2 bn = *(const float2*)&biasN[c];
                v0 += bn.x; v1 += bn.y; v2 += bn.x; v3 += bn.y;
            }
            const size_t o0 = (size_t)r0 * ldc + c;
            const size_t o1 = (size_t)r1 * ldc + c;
            if (resid){
                float2 x0 = *(const float2*)&resid[o0];
                float2 x1 = *(const float2*)&resid[o1];
                v0 += x0.x; v1 += x0.y; v2 += x1.x; v3 += x1.y;
            }
            if (Cf){
                *(float2*)&Cf[o0] = make_float2(v0, v1);
                *(float2*)&Cf[o1] = make_float2(v2, v3);
            }
            if (Ch){
                *(uint32_t*)&Ch[o0] = pack_h2(v0, v1);
                *(uint32_t*)&Ch[o1] = pack_h2(v2, v3);
            }
        }
    }
}

// ---------------- weight convert/transpose (+ zero u) ----------------
__global__ void __launch_bounds__(256) wconvT(const float* __restrict__ wq, const float* __restrict__ wk,
                                              const float* __restrict__ wv, const float* __restrict__ wo_,
                                              u16* __restrict__ wA, u16* __restrict__ wB,
                                              float* __restrict__ u)
{
    __shared__ float t[32][33];
    int z = blockIdx.z;
    int r0 = blockIdx.y * 32, c0 = blockIdx.x * 32;
    if (z == 3 && blockIdx.x == 0 && blockIdx.y == 0){
        u[threadIdx.x] = 0.f; u[threadIdx.x + 256] = 0.f;
    }
    const float* src = (z==0) ? wq : (z==1) ? wk : (z==2) ? wv : wo_;
    u16* dst = (z==0) ? wA : (z==1) ? wB : (z==2) ? (wB + CC2) : (wA + CC2);
    int tx = threadIdx.x & 31, ty = threadIdx.x >> 5;   // 32x8
    if (z < 3){
        #pragma unroll
        for (int i = 0; i < 4; i++)
            t[ty + 8*i][tx] = src[(size_t)(r0 + ty + 8*i)*CC + c0 + tx];
        __syncthreads();
        #pragma unroll
        for (int i = 0; i < 4; i++)
            dst[(size_t)(c0 + ty + 8*i)*CC + r0 + tx] =
                __half_as_ushort(__float2half_rn(t[tx][ty + 8*i]));
    } else {
        #pragma unroll
        for (int i = 0; i < 4; i++){
            size_t o = (size_t)(r0 + ty + 8*i)*CC + c0 + tx;
            dst[o] = __half_as_ushort(__float2half_rn(src[o]));
        }
    }
}

// ---------------- smallvec: u += WkT bq (atomic partials) ; bp = Wo bv + bo ----------------
__global__ void __launch_bounds__(256) smallvec(const float* __restrict__ wk, const float* __restrict__ wo_,
                                                const float* __restrict__ bq, const float* __restrict__ bv,
                                                const float* __restrict__ bo,
                                                float* __restrict__ u, float* __restrict__ bp)
{
    int blk = blockIdx.x;   // 0..15
    int tid = threadIdx.x;
    if (blk < 8){
        // u part: rows o in [blk*64, blk*64+64), cols c = tid, tid+256 (coalesced)
        int o0 = blk * 64;
        #pragma unroll
        for (int h = 0; h < 2; h++){
            int c = tid + h * 256;
            float s = 0.f;
            #pragma unroll 8
            for (int o = 0; o < 64; o++)
                s += wk[(size_t)(o0 + o) * CC + c] * bq[o0 + o];
            atomicAdd(&u[c], s);
        }
    } else {
        // bp: warp per row o; 8 warps x 8 rows
        int w = tid >> 5, lane = tid & 31;
        int obase = (blk - 8) * 64 + w * 8;
        for (int r = 0; r < 8; r++){
            int o = obase + r;
            float s = 0.f;
            for (int c = lane; c < CC; c += 32)
                s += wo_[(size_t)o * CC + c] * bv[c];
            #pragma unroll
            for (int k = 16; k; k >>= 1) s += __shfl_xor_sync(0xffffffffu, s, k);
            if (!lane) bp[o] = bo[o] + s;
        }
    }
}

// ---------------- cvec: c[b][j] = scl * hT[b][j]·u ----------------
__global__ void __launch_bounds__(256) cvec(const u16* __restrict__ hT, const float* __restrict__ u,
                                            float* __restrict__ cv, float scl)
{
    int gw = (blockIdx.x * 256 + threadIdx.x) >> 5;   // 0..16383
    int lane = threadIdx.x & 31;
    const u16* row = hT + (size_t)gw * 512;
    float s = 0.f;
    for (int c = lane; c < 512; c += 32) s += h2f(row[c]) * u[c];
    #pragma unroll
    for (int k = 16; k; k >>= 1) s += __shfl_xor_sync(0xffffffffu, s, k);
    if (!lane) cv[gw] = s * scl;
}

// ---------------- GroupNorm partial stats (512 blocks) ----------------
__global__ void __launch_bounds__(256) gn_stats_part(const float* __restrict__ x, float2* __restrict__ part)
{
    int bg = blockIdx.x >> 3, ch = blockIdx.x & 7;
    const float4* xp = (const float4*)(x + (size_t)bg * 131072 + (size_t)ch * 16384);
    int tid = threadIdx.x;
    float s = 0.f, ss = 0.f;
    #pragma unroll 4
    for (int i = tid; i < 4096; i += 256){
        float4 v = xp[i];
        s  += v.x + v.y + v.z + v.w;
        ss += v.x*v.x + v.y*v.y + v.z*v.z + v.w*v.w;
    }
    __shared__ float rs[8], rss[8];
    #pragma unroll
    for (int o = 16; o; o >>= 1){
        s  += __shfl_xor_sync(0xffffffffu, s,  o);
        ss += __shfl_xor_sync(0xffffffffu, ss, o);
    }
    if ((tid & 31) == 0){ rs[tid>>5] = s; rss[tid>>5] = ss; }
    __syncthreads();
    if (tid == 0){
        float t = 0.f, t2 = 0.f;
        #pragma unroll
        for (int i = 0; i < 8; i++){ t += rs[i]; t2 += rss[i]; }
        part[blockIdx.x] = make_float2(t, t2);
    }
}

// ---------------- GroupNorm apply -> hT [L][C] and h [C][L], both fp16 ----------------
__global__ void __launch_bounds__(256) gn_apply_t(const float* __restrict__ x,
                                                  const float2* __restrict__ part,
                                                  const float* __restrict__ gamma,
                                                  const float* __restrict__ beta,
                                                  u16* __restrict__ hT, u16* __restrict__ h)
{
    __shared__ float tile[64][33];
    int b = blockIdx.z, g = blockIdx.y, l0 = blockIdx.x * 32;
    float t = 0.f, t2 = 0.f;
    #pragma unroll
    for (int i = 0; i < 8; i++){
        float2 p = part[(b*NGRP + g)*8 + i];
        t += p.x; t2 += p.y;
    }
    const float n = (float)(CPG * LLEN);
    float mean = t / n;
    float var  = t2 / n - mean*mean;
    float inv  = rsqrtf(var + 1e-6f);

    const float* xp = x + ((size_t)b*CC + (size_t)g*CPG) * LLEN;
    u16* hp = h + ((size_t)b*CC + (size_t)g*CPG) * LLEN;
    int tid = threadIdx.x;
    #pragma unroll
    for (int i = 0; i < 8; i++){
        int idx = tid + i*256; int c = idx >> 5, l = idx & 31;
        float v = xp[(size_t)c*LLEN + l0 + l];
        float r = (v - mean) * inv * gamma[g*CPG + c] + beta[g*CPG + c];
        tile[c][l] = r;
        hp[(size_t)c*LLEN + l0 + l] = __half_as_ushort(__float2half_rn(r));
    }
    __syncthreads();
    size_t base = (size_t)b * LLEN * CC;
    #pragma unroll
    for (int i = 0; i < 8; i++){
        int idx = tid + i*256; int l = idx >> 6, c = idx & 63;
        size_t o = base + (size_t)(l0 + l)*CC + g*CPG + c;
        hT[o] = __half_as_ushort(__float2half_rn(tile[c][l]));
    }
}

// ---------------- row softmax over fp16, in place ----------------
__global__ void __launch_bounds__(256) softmax_kernel(u16* __restrict__ S)
{
    size_t ob = (size_t)blockIdx.x * LLEN;
    int tid = threadIdx.x;
    int base = tid * 8;
    uint4 hv = *(uint4*)&S[ob + base];
    float v[8];
    {
        uint32_t hw[4] = {hv.x, hv.y, hv.z, hv.w};
        #pragma unroll
        for (int i = 0; i < 4; i++){
            float2 h2 = __half22float2(*(__half2*)&hw[i]);
            v[2*i] = h2.x; v[2*i+1] = h2.y;
        }
    }
    float mx = -1e30f;
    #pragma unroll
    for (int i = 0; i < 8; i++) mx = fmaxf(mx, v[i]);
    __shared__ float rmax[8], rsum[8];
    #pragma unroll
    for (int o = 16; o; o >>= 1) mx = fmaxf(mx, __shfl_xor_sync(0xffffffffu, mx, o));
    if ((tid & 31) == 0) rmax[tid >> 5] = mx;
    __syncthreads();
    float m = rmax[0];
    #pragma unroll
    for (int i = 1; i < 8; i++) m = fmaxf(m, rmax[i]);
    float sm = 0.f;
    #pragma unroll
    for (int i = 0; i < 8; i++){ v[i] = __expf(v[i] - m); sm += v[i]; }
    #pragma unroll
    for (int o = 16; o; o >>= 1) sm += __shfl_xor_sync(0xffffffffu, sm, o);
    if ((tid & 31) == 0) rsum[tid >> 5] = sm;
    __syncthreads();
    float tot = 0.f;
    #pragma unroll
    for (int i = 0; i < 8; i++) tot += rsum[i];
    float inv = 1.f / tot;
    uint32_t ho[4];
    #pragma unroll
    for (int i = 0; i < 4; i++)
        ho[i] = pack_h2(v[2*i] * inv, v[2*i+1] * inv);
    *(uint4*)&S[ob + base] = make_uint4(ho[0], ho[1], ho[2], ho[3]);
}

// ---------------- launch ----------------
extern "C" void kernel_launch(void* const* d_in, const int* in_sizes, int n_in,
                              void* d_out, int out_size)
{
    const float* x     = (const float*)d_in[0];
    const float* gamma = (const float*)d_in[1];
    const float* beta  = (const float*)d_in[2];
    const float* wq    = (const float*)d_in[3];
    const float* bq    = (const float*)d_in[4];
    const float* wk    = (const float*)d_in[5];
    // bk (d_in[6]) cancels inside softmax — unused
    const float* wv    = (const float*)d_in[7];
    const float* bv    = (const float*)d_in[8];
    const float* wo    = (const float*)d_in[9];
    const float* bo    = (const float*)d_in[10];
    float* out = (float*)d_out;

    u16 *hT,*h,*hp,*g,*s,*wA,*wB,*wM;
    float *u, *bp, *cv;
    float2 *part;
    cudaGetSymbolAddress((void**)&hT, g_hT);
    cudaGetSymbolAddress((void**)&h,  g_h);
    cudaGetSymbolAddress((void**)&hp, g_hp);
    cudaGetSymbolAddress((void**)&g,  g_g);
    cudaGetSymbolAddress((void**)&s,  g_s);
    cudaGetSymbolAddress((void**)&wA, g_wA);
    cudaGetSymbolAddress((void**)&wB, g_wB);
    cudaGetSymbolAddress((void**)&wM, g_wM);
    cudaGetSymbolAddress((void**)&u,  g_u);
    cudaGetSymbolAddress((void**)&bp, g_bp);
    cudaGetSymbolAddress((void**)&cv, g_cv);
    cudaGetSymbolAddress((void**)&part, g_part);

    cudaFuncSetAttribute(hmma_gemm, cudaFuncAttributeMaxDynamicSharedMemorySize, DYN_SMEM);

    const long LL = (long)LLEN * LLEN;
    const float scl = 1.0f / sqrtf((float)CC);

    gn_stats_part<<<512, 256>>>(x, part);
    wconvT<<<dim3(16,16,4), 256>>>(wq, wk, wv, wo, wA, wB, u);
    // {M, Wov} = batched 512x512x512: z=0: wqT*wkT^T ; z=1: wo*wvT^T
    hmma_gemm<<<dim3(4,4,2), 128, DYN_SMEM>>>(wA, wB,
        CC, CC, CC, CC, (long)CC2, (long)CC2, (long)CC2,
        nullptr, wM, nullptr, nullptr, 0L, nullptr, 1.f);
    smallvec<<<16, 256>>>(wk, wo, bq, bv, bo, u, bp);
    gn_apply_t<<<dim3(LLEN/32, NGRP, BB), 256>>>(x, part, gamma, beta, hT, h);
    cvec<<<2048, 256>>>(hT, u, cv, scl);

    dim3 blk(128);
    // h'T[j,c] = sum_c' hT[j,c'] M[c,c']       M=2048, N=512, K=512
    hmma_gemm<<<dim3(4,16,BB), blk, DYN_SMEM>>>(hT, wM,
        CC, CC, CC, CC, (long)CL, 0L, (long)CL,
        nullptr, hp, nullptr, nullptr, 0L, nullptr, 1.f);
    // S[i,j] = scl*(hT[i]·h'T[j]) + cv[b][j]   M=N=2048, K=512
    hmma_gemm<<<dim3(16,16,BB), blk, DYN_SMEM>>>(hT, hp,
        CC, CC, CC, LLEN, (long)CL, (long)CL, LL,
        nullptr, s, nullptr, cv, (long)LLEN, nullptr, scl);

    softmax_kernel<<<BB*LLEN, 256>>>(s);

    // gT[i,c] = sum_j P[i,j] h[c,j]            M=2048, N=512, K=2048
    hmma_gemm<<<dim3(4,16,BB), blk, DYN_SMEM>>>(s, h,
        LLEN, LLEN, LLEN, CC, LL, (long)CL, (long)CL,
        nullptr, g, nullptr, nullptr, 0L, nullptr, 1.f);
    // out[o,l] = x + sum_c' Wov[o,c'] gT[l,c'] + bp[o]   M=512, N=2048, K=512
    hmma_gemm<<<dim3(16,4,BB), blk, DYN_SMEM>>>(wM + CC2, g,
        CC, CC, CC, LLEN, 0L, (long)CL, (long)CL,
        out, nullptr, bp, nullptr, 0L, x, 1.f);
}

// round 12
// speedup vs baseline: 3.0278x; 1.0568x over previous
#include <cuda_runtime.h>
#include <cuda_bf16.h>
#include <cuda_fp16.h>
#include <cstdint>
#include <math.h>

#define BB 8
#define CC 512
#define LLEN 2048
#define NGRP 8
#define CPG 64
#define CL (CC*LLEN)
#define CC2 (CC*CC)
typedef unsigned short u16;

// ---------------- scratch ----------------
__device__ u16 g_hT[(size_t)BB*CL];          // hT [B][L][C] fp16
__device__ u16 g_h [(size_t)BB*CL];          // h  [B][C][L] fp16
__device__ u16 g_hp[(size_t)BB*CL];          // h'T = (M h)T [B][L][C]
__device__ u16 g_g [(size_t)BB*CL];          // gT = (P h)T [B][L][C]
__device__ u16 g_s [(size_t)BB*LLEN*LLEN];   // S [B][L][L]
__device__ u16 g_wA[2*CC2];                  // {wqT, wo} fp16
__device__ u16 g_wB[2*CC2];                  // {wkT, wvT} fp16
__device__ u16 g_wM[2*CC2];                  // {M=WqT*Wk, Wov=Wo*Wv} fp16
__device__ float g_u [CC];                   // WkT * bq
__device__ float g_bp[CC];                   // Wo*bv + bo
__device__ float g_cv[BB*LLEN];              // c_j per (b,j), pre-scaled
__device__ float2 g_part[512];               // GN partial (sum, sumsq)

// ---------------- helpers ----------------
__device__ __forceinline__ uint32_t smem_u32(const void* p){
    uint32_t a;
    asm("{ .reg .u64 t; cvta.to.shared.u64 t, %1; cvt.u32.u64 %0, t; }" : "=r"(a) : "l"(p));
    return a;
}
__device__ __forceinline__ void cp16(uint32_t s, const void* g){
    asm volatile("cp.async.cg.shared.global [%0], [%1], 16;" :: "r"(s), "l"(g));
}
#define CP_COMMIT() asm volatile("cp.async.commit_group;" ::: "memory")
#define CP_WAIT1()  asm volatile("cp.async.wait_group 1;" ::: "memory")
#define CP_WAIT0()  asm volatile("cp.async.wait_group 0;" ::: "memory")

#define LDX4(r0,r1,r2,r3,addr) \
    asm volatile("ldmatrix.sync.aligned.m8n8.x4.shared.b16 {%0,%1,%2,%3}, [%4];" \
        : "=r"(r0), "=r"(r1), "=r"(r2), "=r"(r3) : "r"(addr))

#define MMA_F16(d, a, b) \
    asm volatile("mma.sync.aligned.m16n8k16.row.col.f32.f16.f16.f32 " \
        "{%0,%1,%2,%3}, {%4,%5,%6,%7}, {%8,%9}, {%0,%1,%2,%3};" \
        : "+f"((d)[0]), "+f"((d)[1]), "+f"((d)[2]), "+f"((d)[3]) \
        : "r"((a)[0]), "r"((a)[1]), "r"((a)[2]), "r"((a)[3]), "r"((b)[0]), "r"((b)[1]))

__device__ __forceinline__ uint32_t pack_h2(float v0, float v1){
    __half2 h = __floats2half2_rn(v0, v1);
    return *(uint32_t*)&h;
}

// ---------------- fp16 HMMA GEMM: tile 128x128, 128 thr, warp 64x64, BK=64, 3-stage, 2 CTA/SM ----------------
#define OFF_A 0
#define OFF_B 16384
#define STG_B 32768
#define NSTAGE 3
#define DYN_SMEM (NSTAGE*STG_B + 128)

__global__ void __launch_bounds__(128, 2)
hmma_gemm(const u16* __restrict__ A, const u16* __restrict__ B,
          int K, int lda, int ldb, int ldc, long sA, long sB, long sC,
          float* __restrict__ Cf, u16* __restrict__ Ch,
          const float* __restrict__ biasM, const float* __restrict__ biasN, long sBN,
          const float* __restrict__ resid, float scale)
{
    extern __shared__ char dsm[];
    const uint32_t sbase = (smem_u32(dsm) + 127u) & ~127u;
    const int tid = threadIdx.x, lane = tid & 31, wid = tid >> 5;
    const int warpM = (wid & 1) * 64, warpN = (wid >> 1) * 64;
    const int bz = blockIdx.z;
    A += (size_t)bz * sA;
    B += (size_t)bz * sB;
    if (Cf)    Cf    += (size_t)bz * sC;
    if (Ch)    Ch    += (size_t)bz * sC;
    if (resid) resid += (size_t)bz * sC;
    if (biasN) biasN += (size_t)bz * sBN;
    const int m0 = blockIdx.y * 128, n0 = blockIdx.x * 128;
    const int niter = K >> 6;

    const int c_row = tid >> 3, c_seg = tid & 7;
    const uint32_t c_cb = (uint32_t)(c_seg * 16);

    auto issue = [&](int kt){
        const int kk = kt * 64;
        const uint32_t sb = sbase + (kt % NSTAGE) * STG_B;
        #pragma unroll
        for (int j = 0; j < 8; j++){
            const int row = c_row + j * 16;
            const uint32_t sw = (uint32_t)((row & 7) << 4);
            cp16(sb + OFF_A + row * 128 + (c_cb ^ sw),
                 A + (size_t)(m0 + row) * lda + kk + c_seg * 8);
        }
        #pragma unroll
        for (int j = 0; j < 8; j++){
            const int row = c_row + j * 16;
            const uint32_t sw = (uint32_t)((row & 7) << 4);
            cp16(sb + OFF_B + row * 128 + (c_cb ^ sw),
                 B + (size_t)(n0 + row) * ldb + kk + c_seg * 8);
        }
        CP_COMMIT();
    };

    float acc[4][8][4];
    #pragma unroll
    for (int i = 0; i < 4; i++)
        #pragma unroll
        for (int j = 0; j < 8; j++)
            #pragma unroll
            for (int t = 0; t < 4; t++) acc[i][j][t] = 0.f;

    const int aRow0 = warpM + (lane & 15);
    const uint32_t aSw = (uint32_t)((aRow0 & 7) << 4);
    const uint32_t aC  = (uint32_t)((lane >> 4) << 4);
    const int bRow0 = warpN + ((lane >> 4) << 3) + (lane & 7);
    const uint32_t bSw = (uint32_t)((bRow0 & 7) << 4);
    const uint32_t bC  = (uint32_t)(((lane >> 3) & 1) << 4);

    issue(0); if (niter > 1) issue(1);

    for (int kt = 0; kt < niter; kt++){
        if (kt + 1 < niter) CP_WAIT1(); else CP_WAIT0();
        __syncthreads();
        if (kt + 2 < niter) issue(kt + 2);
        const uint32_t sb = sbase + (kt % NSTAGE) * STG_B;

        #pragma unroll
        for (int ko = 0; ko < 4; ko++){
            const uint32_t kb = (uint32_t)(ko * 32);
            uint32_t a_f[4][4], b_f[4][4];
            #pragma unroll
            for (int p = 0; p < 4; p++){
                uint32_t bd = sb + OFF_B + (uint32_t)((bRow0 + p*16) * 128) + ((kb + bC) ^ bSw);
                LDX4(b_f[p][0], b_f[p][1], b_f[p][2], b_f[p][3], bd);
            }
            #pragma unroll
            for (int mt = 0; mt < 4; mt++){
                uint32_t ad = sb + OFF_A + (uint32_t)((aRow0 + (mt&1)*16 + (mt>>1)*32) * 128) + ((kb + aC) ^ aSw);
                LDX4(a_f[mt][0], a_f[mt][1], a_f[mt][2], a_f[mt][3], ad);
            }
            #pragma unroll
            for (int mt = 0; mt < 4; mt++)
                #pragma unroll
                for (int nt = 0; nt < 8; nt++)
                    MMA_F16(acc[mt][nt], a_f[mt], &b_f[nt >> 1][(nt & 1) * 2]);
        }
        __syncthreads();
    }

    // ---- epilogue ----
    #pragma unroll
    for (int mt = 0; mt < 4; mt++){
        const int mrow = (mt&1)*16 + (mt>>1)*32;
        const int r0 = m0 + warpM + mrow + (lane >> 2);
        const int r1 = r0 + 8;
        const float bm0 = biasM ? biasM[r0] : 0.f;
        const float bm1 = biasM ? biasM[r1] : 0.f;
        #pragma unroll
        for (int nt = 0; nt < 8; nt++){
            const int c = n0 + warpN + nt * 8 + ((lane & 3) << 1);
            float v0 = acc[mt][nt][0] * scale + bm0;
            float v1 = acc[mt][nt][1] * scale + bm0;
            float v2 = acc[mt][nt][2] * scale + bm1;
            float v3 = acc[mt][nt][3] * scale + bm1;
            if (biasN){
                float2 bn = *(const float2*)&biasN[c];
                v0 += bn.x; v1 += bn.y; v2 += bn.x; v3 += bn.y;
            }
            const size_t o0 = (size_t)r0 * ldc + c;
            const size_t o1 = (size_t)r1 * ldc + c;
            if (resid){
                float2 x0 = *(const float2*)&resid[o0];
                float2 x1 = *(const float2*)&resid[o1];
                v0 += x0.x; v1 += x0.y; v2 += x1.x; v3 += x1.y;
            }
            if (Cf){
                *(float2*)&Cf[o0] = make_float2(v0, v1);
                *(float2*)&Cf[o1] = make_float2(v2, v3);
            }
            if (Ch){
                *(uint32_t*)&Ch[o0] = pack_h2(v0, v1);
                *(uint32_t*)&Ch[o1] = pack_h2(v2, v3);
            }
        }
    }
}

// ---------------- p1: fused prologue ----------------
// blocks [0,512):    GN partial stats
// blocks [512,1536): weight convert/transpose
// blocks [1536,1552): u[c] = sum_o wk[o][c]*bq[o]     (16 blocks x 32 cols)
// blocks [1552,1616): bp[o] = bo[o] + sum_c wo[o][c]*bv[c]  (64 blocks x 8 rows)
__global__ void __launch_bounds__(256) p1(const float* __restrict__ x, float2* __restrict__ part,
                                          const float* __restrict__ wq, const float* __restrict__ wk,
                                          const float* __restrict__ wv, const float* __restrict__ wo_,
                                          u16* __restrict__ wA, u16* __restrict__ wB,
                                          const float* __restrict__ bq, const float* __restrict__ bv,
                                          const float* __restrict__ bo,
                                          float* __restrict__ u, float* __restrict__ bp)
{
    __shared__ float buf[33*32];
    const int blk = blockIdx.x, tid = threadIdx.x;
    if (blk < 512){
        // ---- GN partial stats ----
        const float4* xp = (const float4*)(x + (size_t)blk * 16384);
        float s = 0.f, ss = 0.f;
        #pragma unroll 4
        for (int i = tid; i < 4096; i += 256){
            float4 v = xp[i];
            s  += v.x + v.y + v.z + v.w;
            ss += v.x*v.x + v.y*v.y + v.z*v.z + v.w*v.w;
        }
        #pragma unroll
        for (int o = 16; o; o >>= 1){
            s  += __shfl_xor_sync(0xffffffffu, s,  o);
            ss += __shfl_xor_sync(0xffffffffu, ss, o);
        }
        if ((tid & 31) == 0){ buf[tid>>5] = s; buf[8 + (tid>>5)] = ss; }
        __syncthreads();
        if (tid == 0){
            float t = 0.f, t2 = 0.f;
            #pragma unroll
            for (int i = 0; i < 8; i++){ t += buf[i]; t2 += buf[8+i]; }
            part[blk] = make_float2(t, t2);
        }
    } else if (blk < 1536){
        // ---- weight convert/transpose ----
        int idx = blk - 512;
        int z = idx >> 8, rem = idx & 255;
        int c0 = (rem & 15) * 32, r0 = (rem >> 4) * 32;
        const float* src = (z==0) ? wq : (z==1) ? wk : (z==2) ? wv : wo_;
        u16* dst = (z==0) ? wA : (z==1) ? wB : (z==2) ? (wB + CC2) : (wA + CC2);
        int tx = tid & 31, ty = tid >> 5;
        if (z < 3){
            #pragma unroll
            for (int i = 0; i < 4; i++)
                buf[(ty + 8*i)*33 + tx] = src[(size_t)(r0 + ty + 8*i)*CC + c0 + tx];
            __syncthreads();
            #pragma unroll
            for (int i = 0; i < 4; i++)
                dst[(size_t)(c0 + ty + 8*i)*CC + r0 + tx] =
                    __half_as_ushort(__float2half_rn(buf[tx*33 + ty + 8*i]));
        } else {
            #pragma unroll
            for (int i = 0; i < 4; i++){
                size_t o = (size_t)(r0 + ty + 8*i)*CC + c0 + tx;
                dst[o] = __half_as_ushort(__float2half_rn(src[o]));
            }
        }
    } else if (blk < 1552){
        // ---- u: 32 cols per block; 8 row-phases x 32 cols ----
        int c0 = (blk - 1536) * 32;
        int ty = tid >> 5, tx = tid & 31;
        float s = 0.f;
        #pragma unroll 8
        for (int o = ty; o < CC; o += 8)
            s += wk[(size_t)o * CC + c0 + tx] * bq[o];
        buf[ty*32 + tx] = s;
        __syncthreads();
        if (ty == 0){
            float t = s;
            #pragma unroll
            for (int i = 1; i < 8; i++) t += buf[i*32 + tx];
            u[c0 + tx] = t;
        }
    } else {
        // ---- bp: 8 rows per block, warp per row, float4 loads ----
        int w = tid >> 5, lane = tid & 31;
        int o = (blk - 1552) * 8 + w;
        const float4* wrow = (const float4*)(wo_ + (size_t)o * CC);
        const float4* bv4  = (const float4*)bv;
        float s = 0.f;
        #pragma unroll
        for (int i = 0; i < 4; i++){
            float4 a = wrow[lane + i*32];
            float4 b = bv4[lane + i*32];
            s += a.x*b.x + a.y*b.y + a.z*b.z + a.w*b.w;
        }
        #pragma unroll
        for (int k = 16; k; k >>= 1) s += __shfl_xor_sync(0xffffffffu, s, k);
        if (!lane) bp[o] = bo[o] + s;
    }
}

// ---------------- cvec: c[b][j] = scl * hT[b][j]·u  (vectorized) ----------------
__global__ void __launch_bounds__(256) cvec(const u16* __restrict__ hT, const float* __restrict__ u,
                                            float* __restrict__ cv, float scl)
{
    int gw = (blockIdx.x * 256 + threadIdx.x) >> 5;   // 0..16383
    int lane = threadIdx.x & 31;
    const uint2* row = (const uint2*)(hT + (size_t)gw * 512);   // 4 halves per uint2
    const float4* u4a = (const float4*)u;
    float s = 0.f;
    #pragma unroll
    for (int i = 0; i < 4; i++){
        uint2 hv = row[lane + i*32];
        float2 a = __half22float2(*(__half2*)&hv.x);
        float2 b = __half22float2(*(__half2*)&hv.y);
        float4 uu = u4a[lane + i*32];
        s += a.x*uu.x + a.y*uu.y + b.x*uu.z + b.y*uu.w;
    }
    #pragma unroll
    for (int k = 16; k; k >>= 1) s += __shfl_xor_sync(0xffffffffu, s, k);
    if (!lane) cv[gw] = s * scl;
}

// ---------------- GroupNorm apply -> hT [L][C] and h [C][L], both fp16 ----------------
__global__ void __launch_bounds__(256) gn_apply_t(const float* __restrict__ x,
                                                  const float2* __restrict__ part,
                                                  const float* __restrict__ gamma,
                                                  const float* __restrict__ beta,
                                                  u16* __restrict__ hT, u16* __restrict__ h)
{
    __shared__ float tile[64][33];
    int b = blockIdx.z, g = blockIdx.y, l0 = blockIdx.x * 32;
    float t = 0.f, t2 = 0.f;
    #pragma unroll
    for (int i = 0; i < 8; i++){
        float2 p = part[(b*NGRP + g)*8 + i];
        t += p.x; t2 += p.y;
    }
    const float n = (float)(CPG * LLEN);
    float mean = t / n;
    float var  = t2 / n - mean*mean;
    float inv  = rsqrtf(var + 1e-6f);

    const float* xp = x + ((size_t)b*CC + (size_t)g*CPG) * LLEN;
    u16* hp = h + ((size_t)b*CC + (size_t)g*CPG) * LLEN;
    int tid = threadIdx.x;
    #pragma unroll
    for (int i = 0; i < 8; i++){
        int idx = tid + i*256; int c = idx >> 5, l = idx & 31;
        float v = xp[(size_t)c*LLEN + l0 + l];
        float r = (v - mean) * inv * gamma[g*CPG + c] + beta[g*CPG + c];
        tile[c][l] = r;
        hp[(size_t)c*LLEN + l0 + l] = __half_as_ushort(__float2half_rn(r));
    }
    __syncthreads();
    size_t base = (size_t)b * LLEN * CC;
    #pragma unroll
    for (int i = 0; i < 8; i++){
        int idx = tid + i*256; int l = idx >> 6, c = idx & 63;
        size_t o = base + (size_t)(l0 + l)*CC + g*CPG + c;
        hT[o] = __half_as_ushort(__float2half_rn(tile[c][l]));
    }
}

// ---------------- row softmax over fp16, in place ----------------
__global__ void __launch_bounds__(256) softmax_kernel(u16* __restrict__ S)
{
    size_t ob = (size_t)blockIdx.x * LLEN;
    int tid = threadIdx.x;
    int base = tid * 8;
    uint4 hv = *(uint4*)&S[ob + base];
    float v[8];
    {
        uint32_t hw[4] = {hv.x, hv.y, hv.z, hv.w};
        #pragma unroll
        for (int i = 0; i < 4; i++){
            float2 h2 = __half22float2(*(__half2*)&hw[i]);
            v[2*i] = h2.x; v[2*i+1] = h2.y;
        }
    }
    float mx = -1e30f;
    #pragma unroll
    for (int i = 0; i < 8; i++) mx = fmaxf(mx, v[i]);
    __shared__ float rmax[8], rsum[8];
    #pragma unroll
    for (int o = 16; o; o >>= 1) mx = fmaxf(mx, __shfl_xor_sync(0xffffffffu, mx, o));
    if ((tid & 31) == 0) rmax[tid >> 5] = mx;
    __syncthreads();
    float m = rmax[0];
    #pragma unroll
    for (int i = 1; i < 8; i++) m = fmaxf(m, rmax[i]);
    float sm = 0.f;
    #pragma unroll
    for (int i = 0; i < 8; i++){ v[i] = __expf(v[i] - m); sm += v[i]; }
    #pragma unroll
    for (int o = 16; o; o >>= 1) sm += __shfl_xor_sync(0xffffffffu, sm, o);
    if ((tid & 31) == 0) rsum[tid >> 5] = sm;
    __syncthreads();
    float tot = 0.f;
    #pragma unroll
    for (int i = 0; i < 8; i++) tot += rsum[i];
    float inv = 1.f / tot;
    uint32_t ho[4];
    #pragma unroll
    for (int i = 0; i < 4; i++)
        ho[i] = pack_h2(v[2*i] * inv, v[2*i+1] * inv);
    *(uint4*)&S[ob + base] = make_uint4(ho[0], ho[1], ho[2], ho[3]);
}

// ---------------- launch ----------------
extern "C" void kernel_launch(void* const* d_in, const int* in_sizes, int n_in,
                              void* d_out, int out_size)
{
    const float* x     = (const float*)d_in[0];
    const float* gamma = (const float*)d_in[1];
    const float* beta  = (const float*)d_in[2];
    const float* wq    = (const float*)d_in[3];
    const float* bq    = (const float*)d_in[4];
    const float* wk    = (const float*)d_in[5];
    // bk cancels inside softmax — unused
    const float* wv    = (const float*)d_in[7];
    const float* bv    = (const float*)d_in[8];
    const float* wo    = (const float*)d_in[9];
    const float* bo    = (const float*)d_in[10];
    float* out = (float*)d_out;

    u16 *hT,*h,*hp,*g,*s,*wA,*wB,*wM;
    float *u, *bp, *cv;
    float2 *part;
    cudaGetSymbolAddress((void**)&hT, g_hT);
    cudaGetSymbolAddress((void**)&h,  g_h);
    cudaGetSymbolAddress((void**)&hp, g_hp);
    cudaGetSymbolAddress((void**)&g,  g_g);
    cudaGetSymbolAddress((void**)&s,  g_s);
    cudaGetSymbolAddress((void**)&wA, g_wA);
    cudaGetSymbolAddress((void**)&wB, g_wB);
    cudaGetSymbolAddress((void**)&wM, g_wM);
    cudaGetSymbolAddress((void**)&u,  g_u);
    cudaGetSymbolAddress((void**)&bp, g_bp);
    cudaGetSymbolAddress((void**)&cv, g_cv);
    cudaGetSymbolAddress((void**)&part, g_part);

    cudaFuncSetAttribute(hmma_gemm, cudaFuncAttributeMaxDynamicSharedMemorySize, DYN_SMEM);

    const long LL = (long)LLEN * LLEN;
    const float scl = 1.0f / sqrtf((float)CC);

    // fused prologue: GN stats | weight convert | u | bp
    p1<<<1616, 256>>>(x, part, wq, wk, wv, wo, wA, wB, bq, bv, bo, u, bp);
    // {M, Wov} = batched 512x512x512
    hmma_gemm<<<dim3(4,4,2), 128, DYN_SMEM>>>(wA, wB,
        CC, CC, CC, CC, (long)CC2, (long)CC2, (long)CC2,
        nullptr, wM, nullptr, nullptr, 0L, nullptr, 1.f);
    gn_apply_t<<<dim3(LLEN/32, NGRP, BB), 256>>>(x, part, gamma, beta, hT, h);
    cvec<<<2048, 256>>>(hT, u, cv, scl);

    dim3 blk(128);
    // h'T[j,c] = sum_c' hT[j,c'] M[c,c']       M=2048, N=512, K=512
    hmma_gemm<<<dim3(4,16,BB), blk, DYN_SMEM>>>(hT, wM,
        CC, CC, CC, CC, (long)CL, 0L, (long)CL,
        nullptr, hp, nullptr, nullptr, 0L, nullptr, 1.f);
    // S[i,j] = scl*(hT[i]·h'T[j]) + cv[b][j]   M=N=2048, K=512
    hmma_gemm<<<dim3(16,16,BB), blk, DYN_SMEM>>>(hT, hp,
        CC, CC, CC, LLEN, (long)CL, (long)CL, LL,
        nullptr, s, nullptr, cv, (long)LLEN, nullptr, scl);

    softmax_kernel<<<BB*LLEN, 256>>>(s);

    // gT[i,c] = sum_j P[i,j] h[c,j]            M=2048, N=512, K=2048
    hmma_gemm<<<dim3(4,16,BB), blk, DYN_SMEM>>>(s, h,
        LLEN, LLEN, LLEN, CC, LL, (long)CL, (long)CL,
        nullptr, g, nullptr, nullptr, 0L, nullptr, 1.f);
    // out[o,l] = x + sum_c' Wov[o,c'] gT[l,c'] + bp[o]   M=512, N=2048, K=512
    hmma_gemm<<<dim3(16,4,BB), blk, DYN_SMEM>>>(wM + CC2, g,
        CC, CC, CC, LLEN, 0L, (long)CL, (long)CL,
        out, nullptr, bp, nullptr, 0L, x, 1.f);
}

// round 13
// speedup vs baseline: 3.1332x; 1.0348x over previous
#include <cuda_runtime.h>
#include <cuda_bf16.h>
#include <cuda_fp16.h>
#include <cstdint>
#include <math.h>

#define BB 8
#define CC 512
#define LLEN 2048
#define NGRP 8
#define CPG 64
#define CL (CC*LLEN)
#define CC2 (CC*CC)
typedef unsigned short u16;

// ---------------- scratch ----------------
__device__ u16 g_hT[(size_t)BB*CL];          // hT [B][L][C] fp16
__device__ u16 g_h [(size_t)BB*CL];          // h  [B][C][L] fp16
__device__ u16 g_hp[(size_t)BB*CL];          // h'T = (M h)T [B][L][C]
__device__ u16 g_g [(size_t)BB*CL];          // gT = (P h)T [B][L][C]
__device__ u16 g_s [(size_t)BB*LLEN*LLEN];   // E = exp(S) [B][L][L]
__device__ u16 g_wA[2*CC2];                  // {wqT, wo} fp16
__device__ u16 g_wB[2*CC2];                  // {wkT, wvT} fp16
__device__ u16 g_wM[2*CC2];                  // {M=WqT*Wk, Wov=Wo*Wv} fp16
__device__ float g_u [CC];                   // WkT * bq
__device__ float g_bp[CC];                   // Wo*bv + bo
__device__ float g_cv[BB*LLEN];              // c_j per (b,j), pre-scaled
__device__ float g_rsum[BB*LLEN];            // row sums of exp(S)
__device__ float2 g_part[512];               // GN partial (sum, sumsq)

// ---------------- helpers ----------------
__device__ __forceinline__ uint32_t smem_u32(const void* p){
    uint32_t a;
    asm("{ .reg .u64 t; cvta.to.shared.u64 t, %1; cvt.u32.u64 %0, t; }" : "=r"(a) : "l"(p));
    return a;
}
__device__ __forceinline__ void cp16(uint32_t s, const void* g){
    asm volatile("cp.async.cg.shared.global [%0], [%1], 16;" :: "r"(s), "l"(g));
}
#define CP_COMMIT() asm volatile("cp.async.commit_group;" ::: "memory")
#define CP_WAIT1()  asm volatile("cp.async.wait_group 1;" ::: "memory")
#define CP_WAIT0()  asm volatile("cp.async.wait_group 0;" ::: "memory")

#define LDX4(r0,r1,r2,r3,addr) \
    asm volatile("ldmatrix.sync.aligned.m8n8.x4.shared.b16 {%0,%1,%2,%3}, [%4];" \
        : "=r"(r0), "=r"(r1), "=r"(r2), "=r"(r3) : "r"(addr))

#define MMA_F16(d, a, b) \
    asm volatile("mma.sync.aligned.m16n8k16.row.col.f32.f16.f16.f32 " \
        "{%0,%1,%2,%3}, {%4,%5,%6,%7}, {%8,%9}, {%0,%1,%2,%3};" \
        : "+f"((d)[0]), "+f"((d)[1]), "+f"((d)[2]), "+f"((d)[3]) \
        : "r"((a)[0]), "r"((a)[1]), "r"((a)[2]), "r"((a)[3]), "r"((b)[0]), "r"((b)[1]))

__device__ __forceinline__ uint32_t pack_h2(float v0, float v1){
    __half2 h = __floats2half2_rn(v0, v1);
    return *(uint32_t*)&h;
}

// ---------------- fp16 HMMA GEMM: tile 128x128, 128 thr, warp 64x64, BK=64, 3-stage, 2 CTA/SM ----------------
// rsum != null: apply exp() after biases, accumulate per-M-row sums (atomic)
// rinv != null: multiply outputs by 1/rinv[row]
#define OFF_A 0
#define OFF_B 16384
#define STG_B 32768
#define NSTAGE 3
#define DYN_SMEM (NSTAGE*STG_B + 128)

__global__ void __launch_bounds__(128, 2)
hmma_gemm(const u16* __restrict__ A, const u16* __restrict__ B,
          int K, int lda, int ldb, int ldc, long sA, long sB, long sC,
          float* __restrict__ Cf, u16* __restrict__ Ch,
          const float* __restrict__ biasM, const float* __restrict__ biasN, long sBN,
          const float* __restrict__ resid,
          float* __restrict__ rsum, const float* __restrict__ rinv, long sRow,
          float scale)
{
    extern __shared__ char dsm[];
    const uint32_t sbase = (smem_u32(dsm) + 127u) & ~127u;
    const int tid = threadIdx.x, lane = tid & 31, wid = tid >> 5;
    const int warpM = (wid & 1) * 64, warpN = (wid >> 1) * 64;
    const int bz = blockIdx.z;
    A += (size_t)bz * sA;
    B += (size_t)bz * sB;
    if (Cf)    Cf    += (size_t)bz * sC;
    if (Ch)    Ch    += (size_t)bz * sC;
    if (resid) resid += (size_t)bz * sC;
    if (biasN) biasN += (size_t)bz * sBN;
    if (rsum)  rsum  += (size_t)bz * sRow;
    if (rinv)  rinv  += (size_t)bz * sRow;
    const int m0 = blockIdx.y * 128, n0 = blockIdx.x * 128;
    const int niter = K >> 6;

    const int c_row = tid >> 3, c_seg = tid & 7;
    const uint32_t c_cb = (uint32_t)(c_seg * 16);

    auto issue = [&](int kt){
        const int kk = kt * 64;
        const uint32_t sb = sbase + (kt % NSTAGE) * STG_B;
        #pragma unroll
        for (int j = 0; j < 8; j++){
            const int row = c_row + j * 16;
            const uint32_t sw = (uint32_t)((row & 7) << 4);
            cp16(sb + OFF_A + row * 128 + (c_cb ^ sw),
                 A + (size_t)(m0 + row) * lda + kk + c_seg * 8);
        }
        #pragma unroll
        for (int j = 0; j < 8; j++){
            const int row = c_row + j * 16;
            const uint32_t sw = (uint32_t)((row & 7) << 4);
            cp16(sb + OFF_B + row * 128 + (c_cb ^ sw),
                 B + (size_t)(n0 + row) * ldb + kk + c_seg * 8);
        }
        CP_COMMIT();
    };

    float acc[4][8][4];
    #pragma unroll
    for (int i = 0; i < 4; i++)
        #pragma unroll
        for (int j = 0; j < 8; j++)
            #pragma unroll
            for (int t = 0; t < 4; t++) acc[i][j][t] = 0.f;

    const int aRow0 = warpM + (lane & 15);
    const uint32_t aSw = (uint32_t)((aRow0 & 7) << 4);
    const uint32_t aC  = (uint32_t)((lane >> 4) << 4);
    const int bRow0 = warpN + ((lane >> 4) << 3) + (lane & 7);
    const uint32_t bSw = (uint32_t)((bRow0 & 7) << 4);
    const uint32_t bC  = (uint32_t)(((lane >> 3) & 1) << 4);

    issue(0); if (niter > 1) issue(1);

    for (int kt = 0; kt < niter; kt++){
        if (kt + 1 < niter) CP_WAIT1(); else CP_WAIT0();
        __syncthreads();
        if (kt + 2 < niter) issue(kt + 2);
        const uint32_t sb = sbase + (kt % NSTAGE) * STG_B;

        #pragma unroll
        for (int ko = 0; ko < 4; ko++){
            const uint32_t kb = (uint32_t)(ko * 32);
            uint32_t a_f[4][4], b_f[4][4];
            #pragma unroll
            for (int p = 0; p < 4; p++){
                uint32_t bd = sb + OFF_B + (uint32_t)((bRow0 + p*16) * 128) + ((kb + bC) ^ bSw);
                LDX4(b_f[p][0], b_f[p][1], b_f[p][2], b_f[p][3], bd);
            }
            #pragma unroll
            for (int mt = 0; mt < 4; mt++){
                uint32_t ad = sb + OFF_A + (uint32_t)((aRow0 + (mt&1)*16 + (mt>>1)*32) * 128) + ((kb + aC) ^ aSw);
                LDX4(a_f[mt][0], a_f[mt][1], a_f[mt][2], a_f[mt][3], ad);
            }
            #pragma unroll
            for (int mt = 0; mt < 4; mt++)
                #pragma unroll
                for (int nt = 0; nt < 8; nt++)
                    MMA_F16(acc[mt][nt], a_f[mt], &b_f[nt >> 1][(nt & 1) * 2]);
        }
        __syncthreads();
    }

    // ---- epilogue ----
    #pragma unroll
    for (int mt = 0; mt < 4; mt++){
        const int mrow = (mt&1)*16 + (mt>>1)*32;
        const int r0 = m0 + warpM + mrow + (lane >> 2);
        const int r1 = r0 + 8;
        const float bm0 = biasM ? biasM[r0] : 0.f;
        const float bm1 = biasM ? biasM[r1] : 0.f;
        float sc0 = 1.f, sc1 = 1.f;
        if (rinv){ sc0 = 1.f / rinv[r0]; sc1 = 1.f / rinv[r1]; }
        float sum0 = 0.f, sum1 = 0.f;
        #pragma unroll
        for (int nt = 0; nt < 8; nt++){
            const int c = n0 + warpN + nt * 8 + ((lane & 3) << 1);
            float v0 = acc[mt][nt][0] * scale + bm0;
            float v1 = acc[mt][nt][1] * scale + bm0;
            float v2 = acc[mt][nt][2] * scale + bm1;
            float v3 = acc[mt][nt][3] * scale + bm1;
            if (rinv){ v0 *= sc0; v1 *= sc0; v2 *= sc1; v3 *= sc1; }
            if (biasN){
                float2 bn = *(const float2*)&biasN[c];
                v0 += bn.x; v1 += bn.y; v2 += bn.x; v3 += bn.y;
            }
            const size_t o0 = (size_t)r0 * ldc + c;
            const size_t o1 = (size_t)r1 * ldc + c;
            if (resid){
                float2 x0 = *(const float2*)&resid[o0];
                float2 x1 = *(const float2*)&resid[o1];
                v0 += x0.x; v1 += x0.y; v2 += x1.x; v3 += x1.y;
            }
            if (rsum){
                v0 = __expf(v0); v1 = __expf(v1);
                v2 = __expf(v2); v3 = __expf(v3);
                sum0 += v0 + v1; sum1 += v2 + v3;
            }
            if (Cf){
                *(float2*)&Cf[o0] = make_float2(v0, v1);
                *(float2*)&Cf[o1] = make_float2(v2, v3);
            }
            if (Ch){
                *(uint32_t*)&Ch[o0] = pack_h2(v0, v1);
                *(uint32_t*)&Ch[o1] = pack_h2(v2, v3);
            }
        }
        if (rsum){
            sum0 += __shfl_xor_sync(0xffffffffu, sum0, 1);
            sum0 += __shfl_xor_sync(0xffffffffu, sum0, 2);
            sum1 += __shfl_xor_sync(0xffffffffu, sum1, 1);
            sum1 += __shfl_xor_sync(0xffffffffu, sum1, 2);
            if ((lane & 3) == 0){
                atomicAdd(&rsum[r0], sum0);
                atomicAdd(&rsum[r1], sum1);
            }
        }
    }
}

// ---------------- p1: fused prologue ----------------
// [0,512): GN partial stats  [512,1536): weight convert  [1536,1552): u
// [1552,1616): bp   [1616,1744): zero cv & rsum
__global__ void __launch_bounds__(256) p1(const float* __restrict__ x, float2* __restrict__ part,
                                          const float* __restrict__ wq, const float* __restrict__ wk,
                                          const float* __restrict__ wv, const float* __restrict__ wo_,
                                          u16* __restrict__ wA, u16* __restrict__ wB,
                                          const float* __restrict__ bq, const float* __restrict__ bv,
                                          const float* __restrict__ bo,
                                          float* __restrict__ u, float* __restrict__ bp,
                                          float* __restrict__ cv, float* __restrict__ rsum)
{
    __shared__ float buf[33*32];
    const int blk = blockIdx.x, tid = threadIdx.x;
    if (blk < 512){
        const float4* xp = (const float4*)(x + (size_t)blk * 16384);
        float s = 0.f, ss = 0.f;
        #pragma unroll 4
        for (int i = tid; i < 4096; i += 256){
            float4 v = xp[i];
            s  += v.x + v.y + v.z + v.w;
            ss += v.x*v.x + v.y*v.y + v.z*v.z + v.w*v.w;
        }
        #pragma unroll
        for (int o = 16; o; o >>= 1){
            s  += __shfl_xor_sync(0xffffffffu, s,  o);
            ss += __shfl_xor_sync(0xffffffffu, ss, o);
        }
        if ((tid & 31) == 0){ buf[tid>>5] = s; buf[8 + (tid>>5)] = ss; }
        __syncthreads();
        if (tid == 0){
            float t = 0.f, t2 = 0.f;
            #pragma unroll
            for (int i = 0; i < 8; i++){ t += buf[i]; t2 += buf[8+i]; }
            part[blk] = make_float2(t, t2);
        }
    } else if (blk < 1536){
        int idx = blk - 512;
        int z = idx >> 8, rem = idx & 255;
        int c0 = (rem & 15) * 32, r0 = (rem >> 4) * 32;
        const float* src = (z==0) ? wq : (z==1) ? wk : (z==2) ? wv : wo_;
        u16* dst = (z==0) ? wA : (z==1) ? wB : (z==2) ? (wB + CC2) : (wA + CC2);
        int tx = tid & 31, ty = tid >> 5;
        if (z < 3){
            #pragma unroll
            for (int i = 0; i < 4; i++)
                buf[(ty + 8*i)*33 + tx] = src[(size_t)(r0 + ty + 8*i)*CC + c0 + tx];
            __syncthreads();
            #pragma unroll
            for (int i = 0; i < 4; i++)
                dst[(size_t)(c0 + ty + 8*i)*CC + r0 + tx] =
                    __half_as_ushort(__float2half_rn(buf[tx*33 + ty + 8*i]));
        } else {
            #pragma unroll
            for (int i = 0; i < 4; i++){
                size_t o = (size_t)(r0 + ty + 8*i)*CC + c0 + tx;
                dst[o] = __half_as_ushort(__float2half_rn(src[o]));
            }
        }
    } else if (blk < 1552){
        int c0 = (blk - 1536) * 32;
        int ty = tid >> 5, tx = tid & 31;
        float s = 0.f;
        #pragma unroll 8
        for (int o = ty; o < CC; o += 8)
            s += wk[(size_t)o * CC + c0 + tx] * bq[o];
        buf[ty*32 + tx] = s;
        __syncthreads();
        if (ty == 0){
            float t = s;
            #pragma unroll
            for (int i = 1; i < 8; i++) t += buf[i*32 + tx];
            u[c0 + tx] = t;
        }
    } else if (blk < 1616){
        int w = tid >> 5, lane = tid & 31;
        int o = (blk - 1552) * 8 + w;
        const float4* wrow = (const float4*)(wo_ + (size_t)o * CC);
        const float4* bv4  = (const float4*)bv;
        float s = 0.f;
        #pragma unroll
        for (int i = 0; i < 4; i++){
            float4 a = wrow[lane + i*32];
            float4 b = bv4[lane + i*32];
            s += a.x*b.x + a.y*b.y + a.z*b.z + a.w*b.w;
        }
        #pragma unroll
        for (int k = 16; k; k >>= 1) s += __shfl_xor_sync(0xffffffffu, s, k);
        if (!lane) bp[o] = bo[o] + s;
    } else {
        int idx = blk - 1616;   // 0..127
        float* dst = (idx < 64) ? cv : rsum;
        dst[(idx & 63) * 256 + tid] = 0.f;
    }
}

// ---------------- GroupNorm apply -> hT [L][C], h [C][L]; fused cv partial ----------------
__global__ void __launch_bounds__(256) gn_apply_t(const float* __restrict__ x,
                                                  const float2* __restrict__ part,
                                                  const float* __restrict__ gamma,
                                                  const float* __restrict__ beta,
                                                  u16* __restrict__ hT, u16* __restrict__ h,
                                                  const float* __restrict__ u,
                                                  float* __restrict__ cv, float scl)
{
    __shared__ float tile[64][33];
    __shared__ float cvb[8][32];
    int b = blockIdx.z, g = blockIdx.y, l0 = blockIdx.x * 32;
    float t = 0.f, t2 = 0.f;
    #pragma unroll
    for (int i = 0; i < 8; i++){
        float2 p = part[(b*NGRP + g)*8 + i];
        t += p.x; t2 += p.y;
    }
    const float n = (float)(CPG * LLEN);
    float mean = t / n;
    float var  = t2 / n - mean*mean;
    float inv  = rsqrtf(var + 1e-6f);

    const float* xp = x + ((size_t)b*CC + (size_t)g*CPG) * LLEN;
    u16* hp = h + ((size_t)b*CC + (size_t)g*CPG) * LLEN;
    int tid = threadIdx.x;
    #pragma unroll
    for (int i = 0; i < 8; i++){
        int idx = tid + i*256; int c = idx >> 5, l = idx & 31;
        float v = xp[(size_t)c*LLEN + l0 + l];
        float r = (v - mean) * inv * gamma[g*CPG + c] + beta[g*CPG + c];
        tile[c][l] = r;
        hp[(size_t)c*LLEN + l0 + l] = __half_as_ushort(__float2half_rn(r));
    }
    __syncthreads();
    size_t base = (size_t)b * LLEN * CC;
    #pragma unroll
    for (int i = 0; i < 8; i++){
        int idx = tid + i*256; int l = idx >> 6, c = idx & 63;
        size_t o = base + (size_t)(l0 + l)*CC + g*CPG + c;
        hT[o] = __half_as_ushort(__float2half_rn(tile[c][l]));
    }
    // cv partial: thread (grp, l) sums 8 channels
    {
        int l = tid & 31, grp = tid >> 5;
        float s = 0.f;
        #pragma unroll
        for (int k = 0; k < 8; k++)
            s += tile[grp*8 + k][l] * u[g*CPG + grp*8 + k];
        cvb[grp][l] = s;
    }
    __syncthreads();
    if (tid < 32){
        float s = 0.f;
        #pragma unroll
        for (int i = 0; i < 8; i++) s += cvb[i][tid];
        atomicAdd(&cv[b*LLEN + l0 + tid], s * scl);
    }
}

// ---------------- launch ----------------
extern "C" void kernel_launch(void* const* d_in, const int* in_sizes, int n_in,
                              void* d_out, int out_size)
{
    const float* x     = (const float*)d_in[0];
    const float* gamma = (const float*)d_in[1];
    const float* beta  = (const float*)d_in[2];
    const float* wq    = (const float*)d_in[3];
    const float* bq    = (const float*)d_in[4];
    const float* wk    = (const float*)d_in[5];
    // bk cancels inside softmax — unused
    const float* wv    = (const float*)d_in[7];
    const float* bv    = (const float*)d_in[8];
    const float* wo    = (const float*)d_in[9];
    const float* bo    = (const float*)d_in[10];
    float* out = (float*)d_out;

    u16 *hT,*h,*hp,*g,*s,*wA,*wB,*wM;
    float *u, *bp, *cv, *rsum;
    float2 *part;
    cudaGetSymbolAddress((void**)&hT, g_hT);
    cudaGetSymbolAddress((void**)&h,  g_h);
    cudaGetSymbolAddress((void**)&hp, g_hp);
    cudaGetSymbolAddress((void**)&g,  g_g);
    cudaGetSymbolAddress((void**)&s,  g_s);
    cudaGetSymbolAddress((void**)&wA, g_wA);
    cudaGetSymbolAddress((void**)&wB, g_wB);
    cudaGetSymbolAddress((void**)&wM, g_wM);
    cudaGetSymbolAddress((void**)&u,  g_u);
    cudaGetSymbolAddress((void**)&bp, g_bp);
    cudaGetSymbolAddress((void**)&cv, g_cv);
    cudaGetSymbolAddress((void**)&rsum, g_rsum);
    cudaGetSymbolAddress((void**)&part, g_part);

    cudaFuncSetAttribute(hmma_gemm, cudaFuncAttributeMaxDynamicSharedMemorySize, DYN_SMEM);

    const long LL = (long)LLEN * LLEN;
    const float scl = 1.0f / sqrtf((float)CC);

    // fused prologue: GN stats | weight convert | u | bp | zero cv,rsum
    p1<<<1744, 256>>>(x, part, wq, wk, wv, wo, wA, wB, bq, bv, bo, u, bp, cv, rsum);
    // {M, Wov} = batched 512x512x512
    hmma_gemm<<<dim3(4,4,2), 128, DYN_SMEM>>>(wA, wB,
        CC, CC, CC, CC, (long)CC2, (long)CC2, (long)CC2,
        nullptr, wM, nullptr, nullptr, 0L, nullptr, nullptr, nullptr, 0L, 1.f);
    // GN apply + hT/h + cv
    gn_apply_t<<<dim3(LLEN/32, NGRP, BB), 256>>>(x, part, gamma, beta, hT, h, u, cv, scl);

    dim3 blk(128);
    // h'T[j,c] = sum_c' hT[j,c'] M[c,c']       M=2048, N=512, K=512
    hmma_gemm<<<dim3(4,16,BB), blk, DYN_SMEM>>>(hT, wM,
        CC, CC, CC, CC, (long)CL, 0L, (long)CL,
        nullptr, hp, nullptr, nullptr, 0L, nullptr, nullptr, nullptr, 0L, 1.f);
    // E[i,j] = exp(scl*(hT[i]·h'T[j]) + cv[b][j]); rsum[b][i] += row sums
    hmma_gemm<<<dim3(16,16,BB), blk, DYN_SMEM>>>(hT, hp,
        CC, CC, CC, LLEN, (long)CL, (long)CL, LL,
        nullptr, s, nullptr, cv, (long)LLEN, nullptr, rsum, nullptr, (long)LLEN, scl);
    // gT[i,c] = (1/rsum[b][i]) * sum_j E[i,j] h[c,j]   M=2048, N=512, K=2048
    hmma_gemm<<<dim3(4,16,BB), blk, DYN_SMEM>>>(s, h,
        LLEN, LLEN, LLEN, CC, LL, (long)CL, (long)CL,
        nullptr, g, nullptr, nullptr, 0L, nullptr, nullptr, rsum, (long)LLEN, 1.f);
    // out[o,l] = x + sum_c' Wov[o,c'] gT[l,c'] + bp[o]   M=512, N=2048, K=512
    hmma_gemm<<<dim3(16,4,BB), blk, DYN_SMEM>>>(wM + CC2, g,
        CC, CC, CC, LLEN, 0L, (long)CL, (long)CL,
        out, nullptr, bp, nullptr, 0L, x, nullptr, nullptr, 0L, 1.f);
}

// round 14
// speedup vs baseline: 3.2895x; 1.0499x over previous
#include <cuda_runtime.h>
#include <cuda_bf16.h>
#include <cuda_fp16.h>
#include <cstdint>
#include <math.h>

#define BB 8
#define CC 512
#define LLEN 2048
#define NGRP 8
#define CPG 64
#define CL (CC*LLEN)
#define CC2 (CC*CC)
typedef unsigned short u16;

// ---------------- scratch ----------------
__device__ u16 g_hT[(size_t)BB*CL];          // hT [B][L][C] fp16
__device__ u16 g_h [(size_t)BB*CL];          // h  [B][C][L] fp16
__device__ u16 g_hp[(size_t)BB*CL];          // h'T = (M h)T [B][L][C]
__device__ u16 g_g [(size_t)BB*CL];          // gT = (P h)T [B][L][C]
__device__ u16 g_s [(size_t)BB*LLEN*LLEN];   // E = exp(S) [B][L][L]
__device__ u16 g_wA[2*CC2];                  // {wqT, wo} fp16
__device__ u16 g_wB[2*CC2];                  // {wkT, wvT} fp16
__device__ u16 g_wM[2*CC2];                  // {M=WqT*Wk, Wov=Wo*Wv} fp16
__device__ float g_u [CC];                   // WkT * bq
__device__ float g_bp[CC];                   // Wo*bv + bo
__device__ float g_cv[BB*LLEN];              // c_j per (b,j), pre-scaled
__device__ float g_rsum[BB*LLEN];            // row sums of exp(S)
__device__ float2 g_part[512];               // GN partial (sum, sumsq)

// ---------------- helpers ----------------
__device__ __forceinline__ uint32_t smem_u32(const void* p){
    uint32_t a;
    asm("{ .reg .u64 t; cvta.to.shared.u64 t, %1; cvt.u32.u64 %0, t; }" : "=r"(a) : "l"(p));
    return a;
}
__device__ __forceinline__ void cp16(uint32_t s, const void* g){
    asm volatile("cp.async.cg.shared.global [%0], [%1], 16;" :: "r"(s), "l"(g));
}
#define CP_COMMIT() asm volatile("cp.async.commit_group;" ::: "memory")
#define CP_WAIT1()  asm volatile("cp.async.wait_group 1;" ::: "memory")
#define CP_WAIT0()  asm volatile("cp.async.wait_group 0;" ::: "memory")

#define LDX4(r0,r1,r2,r3,addr) \
    asm volatile("ldmatrix.sync.aligned.m8n8.x4.shared.b16 {%0,%1,%2,%3}, [%4];" \
        : "=r"(r0), "=r"(r1), "=r"(r2), "=r"(r3) : "r"(addr))

#define MMA_F16(d, a, b) \
    asm volatile("mma.sync.aligned.m16n8k16.row.col.f32.f16.f16.f32 " \
        "{%0,%1,%2,%3}, {%4,%5,%6,%7}, {%8,%9}, {%0,%1,%2,%3};" \
        : "+f"((d)[0]), "+f"((d)[1]), "+f"((d)[2]), "+f"((d)[3]) \
        : "r"((a)[0]), "r"((a)[1]), "r"((a)[2]), "r"((a)[3]), "r"((b)[0]), "r"((b)[1]))

__device__ __forceinline__ uint32_t pack_h2(float v0, float v1){
    __half2 h = __floats2half2_rn(v0, v1);
    return *(uint32_t*)&h;
}

// ---------------- templated fp16 HMMA GEMM ----------------
// MODE flags:
#define F_OUTF32 1
#define F_RESID  4
#define F_BIASN  8
#define F_EXP    16
#define F_RINV   32
#define F_BIASM  64
#define OFF_A 0
#define OFF_B 16384
#define STG_B 32768
#define NSTAGE 3
#define DYN_SMEM (NSTAGE*STG_B + 128)

template<int MODE>
__global__ void __launch_bounds__(128, 2)
hmma_gemm(const u16* __restrict__ A, const u16* __restrict__ B,
          int K, int lda, int ldb, int ldc, long sA, long sB, long sC,
          float* __restrict__ Cf, u16* __restrict__ Ch,
          const float* __restrict__ biasM, const float* __restrict__ biasN, long sBN,
          const float* __restrict__ resid,
          float* __restrict__ rsum, const float* __restrict__ rinv, long sRow,
          float scale)
{
    extern __shared__ char dsm[];
    const uint32_t sbase = (smem_u32(dsm) + 127u) & ~127u;
    const int tid = threadIdx.x, lane = tid & 31, wid = tid >> 5;
    const int warpM = (wid & 1) * 64, warpN = (wid >> 1) * 64;
    const int bz = blockIdx.z;
    A += (size_t)bz * sA;
    B += (size_t)bz * sB;
    if (MODE & F_OUTF32) Cf += (size_t)bz * sC; else Ch += (size_t)bz * sC;
    if (MODE & F_RESID)  resid += (size_t)bz * sC;
    if (MODE & F_BIASN)  biasN += (size_t)bz * sBN;
    if (MODE & F_EXP)    rsum  += (size_t)bz * sRow;
    if (MODE & F_RINV)   rinv  += (size_t)bz * sRow;
    const int m0 = blockIdx.y * 128, n0 = blockIdx.x * 128;
    const int niter = K >> 6;

    const int c_row = tid >> 3, c_seg = tid & 7;
    const uint32_t c_cb = (uint32_t)(c_seg * 16);

    auto issue = [&](int kt){
        const int kk = kt * 64;
        const uint32_t sb = sbase + (kt % NSTAGE) * STG_B;
        #pragma unroll
        for (int j = 0; j < 8; j++){
            const int row = c_row + j * 16;
            const uint32_t sw = (uint32_t)((row & 7) << 4);
            cp16(sb + OFF_A + row * 128 + (c_cb ^ sw),
                 A + (size_t)(m0 + row) * lda + kk + c_seg * 8);
        }
        #pragma unroll
        for (int j = 0; j < 8; j++){
            const int row = c_row + j * 16;
            const uint32_t sw = (uint32_t)((row & 7) << 4);
            cp16(sb + OFF_B + row * 128 + (c_cb ^ sw),
                 B + (size_t)(n0 + row) * ldb + kk + c_seg * 8);
        }
        CP_COMMIT();
    };

    float acc[4][8][4];
    #pragma unroll
    for (int i = 0; i < 4; i++)
        #pragma unroll
        for (int j = 0; j < 8; j++)
            #pragma unroll
            for (int t = 0; t < 4; t++) acc[i][j][t] = 0.f;

    const int aRow0 = warpM + (lane & 15);
    const uint32_t aSw = (uint32_t)((aRow0 & 7) << 4);
    const uint32_t aC  = (uint32_t)((lane >> 4) << 4);
    const int bRow0 = warpN + ((lane >> 4) << 3) + (lane & 7);
    const uint32_t bSw = (uint32_t)((bRow0 & 7) << 4);
    const uint32_t bC  = (uint32_t)(((lane >> 3) & 1) << 4);

    issue(0); if (niter > 1) issue(1);

    for (int kt = 0; kt < niter; kt++){
        if (kt + 1 < niter) CP_WAIT1(); else CP_WAIT0();
        __syncthreads();
        if (kt + 2 < niter) issue(kt + 2);
        const uint32_t sb = sbase + (kt % NSTAGE) * STG_B;

        #pragma unroll
        for (int ko = 0; ko < 4; ko++){
            const uint32_t kb = (uint32_t)(ko * 32);
            uint32_t a_f[4][4], b_f[4][4];
            #pragma unroll
            for (int p = 0; p < 4; p++){
                uint32_t bd = sb + OFF_B + (uint32_t)((bRow0 + p*16) * 128) + ((kb + bC) ^ bSw);
                LDX4(b_f[p][0], b_f[p][1], b_f[p][2], b_f[p][3], bd);
            }
            #pragma unroll
            for (int mt = 0; mt < 4; mt++){
                uint32_t ad = sb + OFF_A + (uint32_t)((aRow0 + (mt&1)*16 + (mt>>1)*32) * 128) + ((kb + aC) ^ aSw);
                LDX4(a_f[mt][0], a_f[mt][1], a_f[mt][2], a_f[mt][3], ad);
            }
            #pragma unroll
            for (int mt = 0; mt < 4; mt++)
                #pragma unroll
                for (int nt = 0; nt < 8; nt++)
                    MMA_F16(acc[mt][nt], a_f[mt], &b_f[nt >> 1][(nt & 1) * 2]);
        }
        // no bottom barrier: prefetch distance 2 of 3 stages + top barrier order stage reuse
    }

    // ---- epilogue (compile-time specialized) ----
    #pragma unroll
    for (int mt = 0; mt < 4; mt++){
        const int mrow = (mt&1)*16 + (mt>>1)*32;
        const int r0 = m0 + warpM + mrow + (lane >> 2);
        const int r1 = r0 + 8;
        float bm0 = 0.f, bm1 = 0.f;
        if (MODE & F_BIASM){ bm0 = biasM[r0]; bm1 = biasM[r1]; }
        float sc0 = 1.f, sc1 = 1.f;
        if (MODE & F_RINV){ sc0 = 1.f / rinv[r0]; sc1 = 1.f / rinv[r1]; }
        float sum0 = 0.f, sum1 = 0.f;
        #pragma unroll
        for (int nt = 0; nt < 8; nt++){
            const int c = n0 + warpN + nt * 8 + ((lane & 3) << 1);
            float v0 = acc[mt][nt][0] * scale + bm0;
            float v1 = acc[mt][nt][1] * scale + bm0;
            float v2 = acc[mt][nt][2] * scale + bm1;
            float v3 = acc[mt][nt][3] * scale + bm1;
            if (MODE & F_RINV){ v0 *= sc0; v1 *= sc0; v2 *= sc1; v3 *= sc1; }
            if (MODE & F_BIASN){
                float2 bn = *(const float2*)&biasN[c];
                v0 += bn.x; v1 += bn.y; v2 += bn.x; v3 += bn.y;
            }
            const size_t o0 = (size_t)r0 * ldc + c;
            const size_t o1 = (size_t)r1 * ldc + c;
            if (MODE & F_RESID){
                float2 x0 = *(const float2*)&resid[o0];
                float2 x1 = *(const float2*)&resid[o1];
                v0 += x0.x; v1 += x0.y; v2 += x1.x; v3 += x1.y;
            }
            if (MODE & F_EXP){
                v0 = __expf(v0); v1 = __expf(v1);
                v2 = __expf(v2); v3 = __expf(v3);
                sum0 += v0 + v1; sum1 += v2 + v3;
            }
            if (MODE & F_OUTF32){
                *(float2*)&Cf[o0] = make_float2(v0, v1);
                *(float2*)&Cf[o1] = make_float2(v2, v3);
            } else {
                *(uint32_t*)&Ch[o0] = pack_h2(v0, v1);
                *(uint32_t*)&Ch[o1] = pack_h2(v2, v3);
            }
        }
        if (MODE & F_EXP){
            sum0 += __shfl_xor_sync(0xffffffffu, sum0, 1);
            sum0 += __shfl_xor_sync(0xffffffffu, sum0, 2);
            sum1 += __shfl_xor_sync(0xffffffffu, sum1, 1);
            sum1 += __shfl_xor_sync(0xffffffffu, sum1, 2);
            if ((lane & 3) == 0){
                atomicAdd(&rsum[r0], sum0);
                atomicAdd(&rsum[r1], sum1);
            }
        }
    }
}

#define MODE_PLAIN 0
#define MODE_S     (F_BIASN|F_EXP)
#define MODE_AV    (F_RINV)
#define MODE_OUT   (F_OUTF32|F_RESID|F_BIASM)

// ---------------- p1: fused prologue ----------------
__global__ void __launch_bounds__(256) p1(const float* __restrict__ x, float2* __restrict__ part,
                                          const float* __restrict__ wq, const float* __restrict__ wk,
                                          const float* __restrict__ wv, const float* __restrict__ wo_,
                                          u16* __restrict__ wA, u16* __restrict__ wB,
                                          const float* __restrict__ bq, const float* __restrict__ bv,
                                          const float* __restrict__ bo,
                                          float* __restrict__ u, float* __restrict__ bp,
                                          float* __restrict__ cv, float* __restrict__ rsum)
{
    __shared__ float buf[33*32];
    const int blk = blockIdx.x, tid = threadIdx.x;
    if (blk < 512){
        const float4* xp = (const float4*)(x + (size_t)blk * 16384);
        float s = 0.f, ss = 0.f;
        #pragma unroll 4
        for (int i = tid; i < 4096; i += 256){
            float4 v = xp[i];
            s  += v.x + v.y + v.z + v.w;
            ss += v.x*v.x + v.y*v.y + v.z*v.z + v.w*v.w;
        }
        #pragma unroll
        for (int o = 16; o; o >>= 1){
            s  += __shfl_xor_sync(0xffffffffu, s,  o);
            ss += __shfl_xor_sync(0xffffffffu, ss, o);
        }
        if ((tid & 31) == 0){ buf[tid>>5] = s; buf[8 + (tid>>5)] = ss; }
        __syncthreads();
        if (tid == 0){
            float t = 0.f, t2 = 0.f;
            #pragma unroll
            for (int i = 0; i < 8; i++){ t += buf[i]; t2 += buf[8+i]; }
            part[blk] = make_float2(t, t2);
        }
    } else if (blk < 1536){
        int idx = blk - 512;
        int z = idx >> 8, rem = idx & 255;
        int c0 = (rem & 15) * 32, r0 = (rem >> 4) * 32;
        const float* src = (z==0) ? wq : (z==1) ? wk : (z==2) ? wv : wo_;
        u16* dst = (z==0) ? wA : (z==1) ? wB : (z==2) ? (wB + CC2) : (wA + CC2);
        int tx = tid & 31, ty = tid >> 5;
        if (z < 3){
            #pragma unroll
            for (int i = 0; i < 4; i++)
                buf[(ty + 8*i)*33 + tx] = src[(size_t)(r0 + ty + 8*i)*CC + c0 + tx];
            __syncthreads();
            #pragma unroll
            for (int i = 0; i < 4; i++)
                dst[(size_t)(c0 + ty + 8*i)*CC + r0 + tx] =
                    __half_as_ushort(__float2half_rn(buf[tx*33 + ty + 8*i]));
        } else {
            #pragma unroll
            for (int i = 0; i < 4; i++){
                size_t o = (size_t)(r0 + ty + 8*i)*CC + c0 + tx;
                dst[o] = __half_as_ushort(__float2half_rn(src[o]));
            }
        }
    } else if (blk < 1552){
        int c0 = (blk - 1536) * 32;
        int ty = tid >> 5, tx = tid & 31;
        float s = 0.f;
        #pragma unroll 8
        for (int o = ty; o < CC; o += 8)
            s += wk[(size_t)o * CC + c0 + tx] * bq[o];
        buf[ty*32 + tx] = s;
        __syncthreads();
        if (ty == 0){
            float t = s;
            #pragma unroll
            for (int i = 1; i < 8; i++) t += buf[i*32 + tx];
            u[c0 + tx] = t;
        }
    } else if (blk < 1616){
        int w = tid >> 5, lane = tid & 31;
        int o = (blk - 1552) * 8 + w;
        const float4* wrow = (const float4*)(wo_ + (size_t)o * CC);
        const float4* bv4  = (const float4*)bv;
        float s = 0.f;
        #pragma unroll
        for (int i = 0; i < 4; i++){
            float4 a = wrow[lane + i*32];
            float4 b = bv4[lane + i*32];
            s += a.x*b.x + a.y*b.y + a.z*b.z + a.w*b.w;
        }
        #pragma unroll
        for (int k = 16; k; k >>= 1) s += __shfl_xor_sync(0xffffffffu, s, k);
        if (!lane) bp[o] = bo[o] + s;
    } else {
        int idx = blk - 1616;   // 0..127
        float* dst = (idx < 64) ? cv : rsum;
        dst[(idx & 63) * 256 + tid] = 0.f;
    }
}

// ---------------- GroupNorm apply: 64x64 tile, paired stores; fused cv partial ----------------
__global__ void __launch_bounds__(256) gn_apply_t(const float* __restrict__ x,
                                                  const float2* __restrict__ part,
                                                  const float* __restrict__ gamma,
                                                  const float* __restrict__ beta,
                                                  u16* __restrict__ hT, u16* __restrict__ h,
                                                  const float* __restrict__ u,
                                                  float* __restrict__ cv, float scl)
{
    __shared__ float tile[64][65];
    __shared__ float cvb[4][64];
    int b = blockIdx.z, g = blockIdx.y, l0 = blockIdx.x * 64;
    float t = 0.f, t2 = 0.f;
    #pragma unroll
    for (int i = 0; i < 8; i++){
        float2 p = part[(b*NGRP + g)*8 + i];
        t += p.x; t2 += p.y;
    }
    const float n = (float)(CPG * LLEN);
    float mean = t / n;
    float var  = t2 / n - mean*mean;
    float inv  = rsqrtf(var + 1e-6f);

    const float* xp = x + ((size_t)b*CC + (size_t)g*CPG) * LLEN;
    u16* hb = h + ((size_t)b*CC + (size_t)g*CPG) * LLEN;
    int tid = threadIdx.x;
    // load + normalize: idx -> (c = idx>>6, l = idx&63); warp = 32 consecutive l (128B)
    #pragma unroll
    for (int i = 0; i < 16; i++){
        int idx = tid + i*256; int c = idx >> 6, l = idx & 63;
        float v = xp[(size_t)c*LLEN + l0 + l];
        tile[c][l] = (v - mean) * inv * gamma[g*CPG + c] + beta[g*CPG + c];
    }
    __syncthreads();
    // h writes: idx -> (c = idx>>5, lp = idx&31), l = 2*lp; warp = 128B
    #pragma unroll
    for (int i = 0; i < 8; i++){
        int idx = tid + i*256; int c = idx >> 5, l = (idx & 31) * 2;
        *(uint32_t*)&hb[(size_t)c*LLEN + l0 + l] = pack_h2(tile[c][l], tile[c][l+1]);
    }
    // hT writes: idx -> (l = idx>>5, cp = idx&31), c = 2*cp; warp = 128B
    size_t base = (size_t)b * LLEN * CC + (size_t)g * CPG;
    #pragma unroll
    for (int i = 0; i < 8; i++){
        int idx = tid + i*256; int l = idx >> 5, c = (idx & 31) * 2;
        *(uint32_t*)&hT[base + (size_t)(l0 + l)*CC + c] = pack_h2(tile[c][l], tile[c+1][l]);
    }
    // cv partial: thread (cgrp = tid>>6, l = tid&63) sums 16 channels
    {
        int l = tid & 63, cgrp = tid >> 6;
        float s = 0.f;
        #pragma unroll
        for (int k = 0; k < 16; k++)
            s += tile[cgrp*16 + k][l] * u[g*CPG + cgrp*16 + k];
        cvb[cgrp][l] = s;
    }
    __syncthreads();
    if (tid < 64){
        float s = cvb[0][tid] + cvb[1][tid] + cvb[2][tid] + cvb[3][tid];
        atomicAdd(&cv[b*LLEN + l0 + tid], s * scl);
    }
}

// ---------------- launch ----------------
extern "C" void kernel_launch(void* const* d_in, const int* in_sizes, int n_in,
                              void* d_out, int out_size)
{
    const float* x     = (const float*)d_in[0];
    const float* gamma = (const float*)d_in[1];
    const float* beta  = (const float*)d_in[2];
    const float* wq    = (const float*)d_in[3];
    const float* bq    = (const float*)d_in[4];
    const float* wk    = (const float*)d_in[5];
    // bk cancels inside softmax — unused
    const float* wv    = (const float*)d_in[7];
    const float* bv    = (const float*)d_in[8];
    const float* wo    = (const float*)d_in[9];
    const float* bo    = (const float*)d_in[10];
    float* out = (float*)d_out;

    u16 *hT,*h,*hp,*g,*s,*wA,*wB,*wM;
    float *u, *bp, *cv, *rsum;
    float2 *part;
    cudaGetSymbolAddress((void**)&hT, g_hT);
    cudaGetSymbolAddress((void**)&h,  g_h);
    cudaGetSymbolAddress((void**)&hp, g_hp);
    cudaGetSymbolAddress((void**)&g,  g_g);
    cudaGetSymbolAddress((void**)&s,  g_s);
    cudaGetSymbolAddress((void**)&wA, g_wA);
    cudaGetSymbolAddress((void**)&wB, g_wB);
    cudaGetSymbolAddress((void**)&wM, g_wM);
    cudaGetSymbolAddress((void**)&u,  g_u);
    cudaGetSymbolAddress((void**)&bp, g_bp);
    cudaGetSymbolAddress((void**)&cv, g_cv);
    cudaGetSymbolAddress((void**)&rsum, g_rsum);
    cudaGetSymbolAddress((void**)&part, g_part);

    cudaFuncSetAttribute(hmma_gemm<MODE_PLAIN>, cudaFuncAttributeMaxDynamicSharedMemorySize, DYN_SMEM);
    cudaFuncSetAttribute(hmma_gemm<MODE_S>,     cudaFuncAttributeMaxDynamicSharedMemorySize, DYN_SMEM);
    cudaFuncSetAttribute(hmma_gemm<MODE_AV>,    cudaFuncAttributeMaxDynamicSharedMemorySize, DYN_SMEM);
    cudaFuncSetAttribute(hmma_gemm<MODE_OUT>,   cudaFuncAttributeMaxDynamicSharedMemorySize, DYN_SMEM);

    const long LL = (long)LLEN * LLEN;
    const float scl = 1.0f / sqrtf((float)CC);

    // fused prologue: GN stats | weight convert | u | bp | zero cv,rsum
    p1<<<1744, 256>>>(x, part, wq, wk, wv, wo, wA, wB, bq, bv, bo, u, bp, cv, rsum);
    // {M, Wov} = batched 512x512x512
    hmma_gemm<MODE_PLAIN><<<dim3(4,4,2), 128, DYN_SMEM>>>(wA, wB,
        CC, CC, CC, CC, (long)CC2, (long)CC2, (long)CC2,
        nullptr, wM, nullptr, nullptr, 0L, nullptr, nullptr, nullptr, 0L, 1.f);
    // GN apply + hT/h + cv
    gn_apply_t<<<dim3(LLEN/64, NGRP, BB), 256>>>(x, part, gamma, beta, hT, h, u, cv, scl);

    dim3 blk(128);
    // h'T[j,c] = sum_c' hT[j,c'] M[c,c']       M=2048, N=512, K=512
    hmma_gemm<MODE_PLAIN><<<dim3(4,16,BB), blk, DYN_SMEM>>>(hT, wM,
        CC, CC, CC, CC, (long)CL, 0L, (long)CL,
        nullptr, hp, nullptr, nullptr, 0L, nullptr, nullptr, nullptr, 0L, 1.f);
    // E[i,j] = exp(scl*(hT[i]·h'T[j]) + cv[b][j]); rsum[b][i] += row sums
    hmma_gemm<MODE_S><<<dim3(16,16,BB), blk, DYN_SMEM>>>(hT, hp,
        CC, CC, CC, LLEN, (long)CL, (long)CL, LL,
        nullptr, s, nullptr, cv, (long)LLEN, nullptr, rsum, nullptr, (long)LLEN, scl);
    // gT[i,c] = (1/rsum[b][i]) * sum_j E[i,j] h[c,j]   M=2048, N=512, K=2048
    hmma_gemm<MODE_AV><<<dim3(4,16,BB), blk, DYN_SMEM>>>(s, h,
        LLEN, LLEN, LLEN, CC, LL, (long)CL, (long)CL,
        nullptr, g, nullptr, nullptr, 0L, nullptr, nullptr, rsum, (long)LLEN, 1.f);
    // out[o,l] = x + sum_c' Wov[o,c'] gT[l,c'] + bp[o]   M=512, N=2048, K=512
    hmma_gemm<MODE_OUT><<<dim3(16,4,BB), blk, DYN_SMEM>>>(wM + CC2, g,
        CC, CC, CC, LLEN, 0L, (long)CL, (long)CL,
        out, nullptr, bp, nullptr, 0L, x, nullptr, nullptr, 0L, 1.f);
}